// round 12
// baseline (speedup 1.0000x reference)
#include <cuda_runtime.h>
#include <cuda_bf16.h>
#include <math.h>

#define NN 50000
#define EE 800000
#define HH 128
#define EDIM 32
#define GG 64
#define AA 16
#define BN_EPS 1e-5f
#define FULLM 0xffffffffu
#define TS 72   // smem tile row stride (floats): conflict-free STS.64/LDS.128

// ---------------- scratch (static device globals; no allocation) ----------------
__device__ float g_y[(size_t)NN * HH];
__device__ float g_u[(size_t)NN * HH];
__device__ float g_h[(size_t)NN * HH];
__device__ float g_sum[HH];
__device__ float g_sumsq[HH];
__device__ float g_pooled[GG * HH];
__device__ int   g_idx64;

// ---------------- int32/int64 index handling ----------------
__device__ __forceinline__ long long read_idx(const void* p, long long i, bool i64) {
    if (i64) return ((const long long*)p)[i];
    return (long long)((const int*)p)[i];
}

__global__ void detect_kernel(const unsigned int* __restrict__ w) {
    __shared__ int f;
    if (threadIdx.x == 0) f = 0;
    __syncthreads();
    int local = 0;
    for (int i = threadIdx.x * 2 + 1; i < 8192; i += 512)
        if (w[i]) local = 1;
    if (local) atomicOr(&f, 1);
    __syncthreads();
    if (threadIdx.x == 0) g_idx64 = f ? 0 : 1;
}

__global__ void zero_stats_kernel() {
    if (threadIdx.x < HH) {
        g_sum[threadIdx.x] = 0.f;
        g_sumsq[threadIdx.x] = 0.f;
    }
}

// ---------------- bf16 2-split helpers ----------------
__device__ __forceinline__ unsigned pack2(float e0, float e1) {
    unsigned r;
    asm("cvt.rn.bf16x2.f32 %0, %1, %2;" : "=r"(r) : "f"(e1), "f"(e0));
    return r;
}
__device__ __forceinline__ void split2(float e0, float e1, unsigned& hi, unsigned& lo) {
    hi = pack2(e0, e1);
    float f0 = __uint_as_float(hi << 16);
    float f1 = __uint_as_float(hi & 0xffff0000u);
    lo = pack2(e0 - f0, e1 - f1);
}
__device__ __forceinline__ void mma_bf16(float& c0, float& c1, float& c2, float& c3,
                                         unsigned a0, unsigned a1, unsigned a2, unsigned a3,
                                         unsigned b0, unsigned b1) {
    asm volatile("mma.sync.aligned.m16n8k16.row.col.f32.bf16.bf16.f32 "
                 "{%0,%1,%2,%3}, {%4,%5,%6,%7}, {%8,%9}, {%0,%1,%2,%3};"
                 : "+f"(c0), "+f"(c1), "+f"(c2), "+f"(c3)
                 : "r"(a0), "r"(a1), "r"(a2), "r"(a3), "r"(b0), "r"(b1));
}

// Stage pre-split B fragments for one k32 block (1024 float4).
__device__ __forceinline__ void stage_bfrag(float4* bfrag, const float* __restrict__ Wmat,
                                            int ldw, int kbase, int tid, int nthreads) {
    for (int idx = tid; idx < 1024; idx += nthreads) {
        int nt = idx >> 6, kc = (idx >> 5) & 1, ln = idx & 31;
        int g2 = ln >> 2, t2 = ln & 3;
        int c = nt * 8 + g2;
        int k0 = kbase + 16 * kc + 2 * t2;
        float w00 = Wmat[c * ldw + k0];
        float w01 = Wmat[c * ldw + k0 + 1];
        float w10 = Wmat[c * ldw + k0 + 8];
        float w11 = Wmat[c * ldw + k0 + 9];
        unsigned bh0, bl0, bh1, bl1;
        split2(w00, w01, bh0, bl0);
        split2(w10, w11, bh1, bl1);
        bfrag[idx] = make_float4(__uint_as_float(bh0), __uint_as_float(bh1),
                                 __uint_as_float(bl0), __uint_as_float(bl1));
    }
}

// Load raw A data (2 rows x one k32 block) as 8 float2.
__device__ __forceinline__ void load_a_raw(const float* __restrict__ row0,
                                           const float* __restrict__ row1,
                                           int kbase, int t, float2 A[8]) {
#pragma unroll
    for (int kc = 0; kc < 2; kc++) {
        int k0 = kbase + 16 * kc + 2 * t;
        A[kc * 4 + 0] = *(const float2*)(row0 + k0);
        A[kc * 4 + 1] = *(const float2*)(row1 + k0);
        A[kc * 4 + 2] = *(const float2*)(row0 + k0 + 8);
        A[kc * 4 + 3] = *(const float2*)(row1 + k0 + 8);
    }
}
__device__ __forceinline__ void split_a(const float2 A[8],
                                        unsigned ahi[2][4], unsigned alo[2][4]) {
#pragma unroll
    for (int kc = 0; kc < 2; kc++) {
        split2(A[kc * 4 + 0].x, A[kc * 4 + 0].y, ahi[kc][0], alo[kc][0]);
        split2(A[kc * 4 + 1].x, A[kc * 4 + 1].y, ahi[kc][1], alo[kc][1]);
        split2(A[kc * 4 + 2].x, A[kc * 4 + 2].y, ahi[kc][2], alo[kc][2]);
        split2(A[kc * 4 + 3].x, A[kc * 4 + 3].y, ahi[kc][3], alo[kc][3]);
    }
}

// ---------------- y = src (copy), 4 float4 per thread for MLP ----------------
__global__ void copy_init_kernel(const float4* __restrict__ src, int n4) {
    int base = blockIdx.x * blockDim.x * 4 + threadIdx.x;
    int s = blockDim.x;
    int i0 = base, i1 = base + s, i2 = base + 2 * s, i3 = base + 3 * s;
    if (i3 < n4) {
        float4 v0 = src[i0], v1 = src[i1], v2 = src[i2], v3 = src[i3];
        ((float4*)g_y)[i0] = v0;
        ((float4*)g_y)[i1] = v1;
        ((float4*)g_y)[i2] = v2;
        ((float4*)g_y)[i3] = v3;
    } else {
        if (i0 < n4) ((float4*)g_y)[i0] = src[i0];
        if (i1 < n4) ((float4*)g_y)[i1] = src[i1];
        if (i2 < n4) ((float4*)g_y)[i2] = src[i2];
    }
}

// ---------------- edge kernel: mma elin + smem-tiled coalesced epilogue ----------------
#define NTILES 50000         // EE/16
#define WTILES 8
__global__ void __launch_bounds__(256, 2) edge_mma_kernel(
    const float* __restrict__ xin_ext, int use_h,
    const float* __restrict__ ea,
    const void* __restrict__ eiv,
    const float* __restrict__ We,   // [128][32] row-major
    const float* __restrict__ be)
{
    __shared__ float4 bfrag[1024];        // 16KB
    __shared__ float be_s[HH];
    __shared__ float sbuf[8][16 * TS];    // per-warp [16 edges][64 cols padded]  36.9KB

    const int tid = threadIdx.x;
    // layer 2: re-zero BN stats for the upcoming gemm (edge2 strictly precedes gemm2,
    // and normalize1 — the last reader of the old stats — precedes edge2)
    if (use_h && blockIdx.x == 0 && tid < HH) {
        g_sum[tid] = 0.f;
        g_sumsq[tid] = 0.f;
    }
    stage_bfrag(bfrag, We, EDIM, 0, tid, 256);
    if (tid < HH) be_s[tid] = be[tid];
    __syncthreads();

    const float* __restrict__ xin = use_h ? g_h : xin_ext;
    const int lane = tid & 31, warp = tid >> 5;
    const int g = lane >> 2, t = lane & 3;
    const bool i64 = (g_idx64 != 0);
    const int half16 = lane >> 4;        // 0/1: which of 2 edges per epilogue iter
    const int li = lane & 15;            // column quad within edge half-row
    float* buf = sbuf[warp];
    const int base = (blockIdx.x * 8 + warp) * WTILES;

    int nt_here = NTILES - base;
    if (nt_here <= 0) return;
    if (nt_here > WTILES) nt_here = WTILES;

    for (int it = 0; it < nt_here; it++) {
        long long e0 = (long long)(base + it) * 16;
        int svC = 0, dvC = 0;
        if (lane < 16) {
            svC = (int)read_idx(eiv, e0 + lane, i64);
            dvC = (int)read_idx(eiv, (long long)EE + e0 + lane, i64);
        }
        float2 Ac[8];
        load_a_raw(ea + (size_t)(e0 + g) * EDIM, ea + (size_t)(e0 + g + 8) * EDIM, 0, t, Ac);

        unsigned ahi[2][4], alo[2][4];
        split_a(Ac, ahi, alo);

#pragma unroll
        for (int h = 0; h < 2; h++) {
            // ---- phase A: mma for cols [h*64, h*64+64), write to smem tile ----
#pragma unroll
            for (int ntl = 0; ntl < 8; ntl++) {
                int nt = h * 8 + ntl;
                float2 b2 = *(const float2*)(be_s + nt * 8 + 2 * t);
                float c0 = b2.x, c1 = b2.y, c2 = b2.x, c3 = b2.y;
#pragma unroll
                for (int kc = 0; kc < 2; kc++) {
                    float4 bf = bfrag[(nt * 2 + kc) * 32 + lane];
                    unsigned bh0 = __float_as_uint(bf.x), bh1 = __float_as_uint(bf.y);
                    unsigned bl0 = __float_as_uint(bf.z), bl1 = __float_as_uint(bf.w);
                    mma_bf16(c0, c1, c2, c3, ahi[kc][0], ahi[kc][1], ahi[kc][2], ahi[kc][3], bh0, bh1);
                    mma_bf16(c0, c1, c2, c3, alo[kc][0], alo[kc][1], alo[kc][2], alo[kc][3], bh0, bh1);
                    mma_bf16(c0, c1, c2, c3, ahi[kc][0], ahi[kc][1], ahi[kc][2], ahi[kc][3], bl0, bl1);
                }
                int cw = ntl * 8 + 2 * t;
                *(float2*)(buf + g * TS + cw)       = make_float2(c0, c1);
                *(float2*)(buf + (g + 8) * TS + cw) = make_float2(c2, c3);
            }
            __syncwarp();

            // ---- phase B: coalesced gather + relu + red, 2 edges x 64 cols per iter ----
#pragma unroll
            for (int g2 = 0; g2 < 4; g2++) {
                float4 m0, m1, xv0, xv1;
                int e0i = 4 * g2 + half16;       // edges e0i and e0i+2
                int e1i = e0i + 2;
                int s0 = __shfl_sync(FULLM, svC, e0i);
                int s1 = __shfl_sync(FULLM, svC, e1i);
                m0 = *(const float4*)(buf + e0i * TS + 4 * li);
                m1 = *(const float4*)(buf + e1i * TS + 4 * li);
                xv0 = *(const float4*)(xin + (size_t)s0 * HH + h * 64 + 4 * li);
                xv1 = *(const float4*)(xin + (size_t)s1 * HH + h * 64 + 4 * li);
                int d0 = __shfl_sync(FULLM, dvC, e0i);
                int d1 = __shfl_sync(FULLM, dvC, e1i);
                {
                    float o0 = fmaxf(m0.x + xv0.x, 0.f);
                    float o1 = fmaxf(m0.y + xv0.y, 0.f);
                    float o2 = fmaxf(m0.z + xv0.z, 0.f);
                    float o3 = fmaxf(m0.w + xv0.w, 0.f);
                    asm volatile("red.global.add.v4.f32 [%0], {%1,%2,%3,%4};"
                                 :: "l"(g_y + (size_t)d0 * HH + h * 64 + 4 * li),
                                    "f"(o0), "f"(o1), "f"(o2), "f"(o3) : "memory");
                }
                {
                    float o0 = fmaxf(m1.x + xv1.x, 0.f);
                    float o1 = fmaxf(m1.y + xv1.y, 0.f);
                    float o2 = fmaxf(m1.z + xv1.z, 0.f);
                    float o3 = fmaxf(m1.w + xv1.w, 0.f);
                    asm volatile("red.global.add.v4.f32 [%0], {%1,%2,%3,%4};"
                                 :: "l"(g_y + (size_t)d1 * HH + h * 64 + 4 * li),
                                    "f"(o0), "f"(o1), "f"(o2), "f"(o3) : "memory");
                }
            }
            __syncwarp();
        }
    }
}

// ---------------- node GEMM + fused BN sums (smem-staged): u = g_y @ W.T + b ----------------
// 512 threads, 16 warps. Warp: 16 rows x 64 cols. Block: 128 rows x 128 cols.
__global__ void __launch_bounds__(512) node_gemm_mma_kernel(
    const float* __restrict__ W,
    const float* __restrict__ b)
{
    __shared__ float4 bfrag[1024];   // restaged per k32 block, 16KB
    __shared__ float b_s[HH];
    __shared__ float s_sum[HH], s_sumsq[HH];

    const int tid = threadIdx.x;
    const int lane = tid & 31, warp = tid >> 5;
    const int g = lane >> 2, t = lane & 3;
    const int colhalf = warp >> 3;
    const int rw = warp & 7;
    const int nt0 = colhalf * 8;
    const int rowbase = blockIdx.x * 128 + rw * 16;
    const bool active = (rowbase < NN);      // NN % 16 == 0
    const bool even = ((t & 1) == 0);
    const int cboff = (t & 2) ? 4 : 0;

    if (tid < HH) {
        b_s[tid] = b[tid];
        s_sum[tid] = 0.f;
        s_sumsq[tid] = 0.f;
    }

    float C[8][4];
#pragma unroll
    for (int nt = 0; nt < 8; nt++)
#pragma unroll
        for (int q = 0; q < 4; q++) C[nt][q] = 0.f;

    for (int kb = 0; kb < 4; kb++) {
        __syncthreads();
        stage_bfrag(bfrag, W, HH, kb * 32, tid, 512);
        __syncthreads();

        if (active) {
            const float* row0 = g_y + (size_t)(rowbase + g) * HH;
            const float* row1 = g_y + (size_t)(rowbase + g + 8) * HH;
            float2 A[8];
            load_a_raw(row0, row1, kb * 32, t, A);
            unsigned ahi[2][4], alo[2][4];
            split_a(A, ahi, alo);

#pragma unroll
            for (int ntl = 0; ntl < 8; ntl++) {
                int nt = nt0 + ntl;
#pragma unroll
                for (int kc = 0; kc < 2; kc++) {
                    float4 bf = bfrag[(nt * 2 + kc) * 32 + lane];
                    unsigned bh0 = __float_as_uint(bf.x), bh1 = __float_as_uint(bf.y);
                    unsigned bl0 = __float_as_uint(bf.z), bl1 = __float_as_uint(bf.w);
                    mma_bf16(C[ntl][0], C[ntl][1], C[ntl][2], C[ntl][3],
                             ahi[kc][0], ahi[kc][1], ahi[kc][2], ahi[kc][3], bh0, bh1);
                    mma_bf16(C[ntl][0], C[ntl][1], C[ntl][2], C[ntl][3],
                             alo[kc][0], alo[kc][1], alo[kc][2], alo[kc][3], bh0, bh1);
                    mma_bf16(C[ntl][0], C[ntl][1], C[ntl][2], C[ntl][3],
                             ahi[kc][0], ahi[kc][1], ahi[kc][2], ahi[kc][3], bl0, bl1);
                }
            }
        }
    }

    if (active) {
        const int orow = rowbase + (even ? g : g + 8);
        float* outp = g_u + (size_t)orow * HH + cboff;
#pragma unroll
        for (int ntl = 0; ntl < 8; ntl++) {
            int nt = nt0 + ntl;
            float c0 = C[ntl][0] + b_s[nt * 8 + 2 * t];
            float c1 = C[ntl][1] + b_s[nt * 8 + 2 * t + 1];
            float c2 = C[ntl][2] + b_s[nt * 8 + 2 * t];
            float c3 = C[ntl][3] + b_s[nt * 8 + 2 * t + 1];

            // ---- BN column sums over this warp's 16 rows -> smem staging ----
            float s0 = c0 + c2, s1 = c1 + c3;
            float q0 = c0 * c0 + c2 * c2, q1 = c1 * c1 + c3 * c3;
#pragma unroll
            for (int m = 4; m <= 16; m <<= 1) {
                s0 += __shfl_xor_sync(FULLM, s0, m);
                s1 += __shfl_xor_sync(FULLM, s1, m);
                q0 += __shfl_xor_sync(FULLM, q0, m);
                q1 += __shfl_xor_sync(FULLM, q1, m);
            }
            if (g == 0) {   // lanes 0-3: one contribution per column pair
                int col = nt * 8 + 2 * t;
                atomicAdd(&s_sum[col], s0);
                atomicAdd(&s_sum[col + 1], s1);
                atomicAdd(&s_sumsq[col], q0);
                atomicAdd(&s_sumsq[col + 1], q1);
            }

            float e0 = even ? c2 : c0;
            float e1 = even ? c3 : c1;
            float r0 = __shfl_xor_sync(FULLM, e0, 1);
            float r1 = __shfl_xor_sync(FULLM, e1, 1);
            float4 o;
            if (even) { o = make_float4(c0, c1, r0, r1); }
            else      { o = make_float4(r0, r1, c2, c3); }
            *(float4*)(outp + nt * 8) = o;
        }
    }

    // ---- flush block sums: 128 global atomics per block ----
    __syncthreads();
    if (tid < HH) {
        atomicAdd(&g_sum[tid], s_sum[tid]);
        atomicAdd(&g_sumsq[tid], s_sumsq[tid]);
    }
}

// ---------------- normalize (stats in-block, 4 float4/thread): h = act(u*scale+shift) ----------------
__global__ void normalize_kernel(int mode, int n4,
                                 const float* __restrict__ gamma,
                                 const float* __restrict__ beta) {
    __shared__ float sc_s[HH], sh_s[HH];
    if (threadIdx.x < HH) {
        int c = threadIdx.x;
        float m = g_sum[c] * (1.f / NN);
        float v = g_sumsq[c] * (1.f / NN) - m * m;
        float rs = rsqrtf(v + BN_EPS);
        float sc = rs * gamma[c];
        sc_s[c] = sc;
        sh_s[c] = beta[c] - m * sc;
    }
    __syncthreads();

    int base = blockIdx.x * blockDim.x * 4 + threadIdx.x;
    int s = blockDim.x;

#pragma unroll
    for (int rep = 0; rep < 1; rep++) {}   // (no-op; keeps structure flat)

    int idx[4] = {base, base + s, base + 2 * s, base + 3 * s};
    float4 v[4];
    bool ok[4];
#pragma unroll
    for (int q = 0; q < 4; q++) {
        ok[q] = (idx[q] < n4);
        if (ok[q]) v[q] = ((const float4*)g_u)[idx[q]];
    }
#pragma unroll
    for (int q = 0; q < 4; q++) {
        if (!ok[q]) continue;
        int c0 = (idx[q] * 4) & 127;
        float4 sc = *(const float4*)(sc_s + c0);
        float4 sh = *(const float4*)(sh_s + c0);
        float4 w = v[q];
        w.x = fmaxf(w.x * sc.x + sh.x, 0.f);
        w.y = fmaxf(w.y * sc.y + sh.y, 0.f);
        w.z = fmaxf(w.z * sc.z + sh.z, 0.f);
        w.w = fmaxf(w.w * sc.w + sh.w, 0.f);
        if (mode == 1) {
            w.x = 1.f / (1.f + expf(-w.x));
            w.y = 1.f / (1.f + expf(-w.y));
            w.z = 1.f / (1.f + expf(-w.z));
            w.w = 1.f / (1.f + expf(-w.w));
        }
        ((float4*)g_h)[idx[q]] = w;
        if (mode == 0) ((float4*)g_y)[idx[q]] = w;   // layer2 accumulator init
    }
}

// ---------------- per-graph mean pooling ----------------
__device__ __forceinline__ int lb_search(const void* bp, int target, bool i64) {
    int l = 0, r = NN;
    while (l < r) {
        int m = (l + r) >> 1;
        if (read_idx(bp, m, i64) < (long long)target) l = m + 1; else r = m;
    }
    return l;
}

__global__ void pool_kernel(const void* __restrict__ batchv) {
    const int g = blockIdx.x, c = threadIdx.x;
    const bool i64 = (g_idx64 != 0);
    int lo = lb_search(batchv, g, i64);
    int hi = lb_search(batchv, g + 1, i64);
    float s0 = 0.f, s1 = 0.f, s2 = 0.f, s3 = 0.f;
    int i = lo;
    for (; i + 3 < hi; i += 4) {
        s0 += g_h[(size_t)i * HH + c];
        s1 += g_h[(size_t)(i + 1) * HH + c];
        s2 += g_h[(size_t)(i + 2) * HH + c];
        s3 += g_h[(size_t)(i + 3) * HH + c];
    }
    for (; i < hi; i++) s0 += g_h[(size_t)i * HH + c];
    float s = (s0 + s1) + (s2 + s3);
    int cnt = hi - lo;
    g_pooled[g * HH + c] = s / fmaxf((float)cnt, 1.f);
}

// ---------------- fused action MLP ----------------
__device__ __forceinline__ void mlp_layer(float* z, const float* p_s,
                                          const float* __restrict__ Wrow,
                                          float bias, float gamma, float beta) {
#pragma unroll
    for (int r = 0; r < GG; r++) z[r] = bias;
    for (int k = 0; k < HH; k += 4) {
        float4 w = *(const float4*)(Wrow + k);
#pragma unroll
        for (int r = 0; r < GG; r++) {
            float4 p = *(const float4*)(p_s + r * HH + k);
            z[r] += w.x * p.x + w.y * p.y + w.z * p.z + w.w * p.w;
        }
    }
    float m = 0.f, s2 = 0.f;
#pragma unroll
    for (int r = 0; r < GG; r++) { m += z[r]; s2 += z[r] * z[r]; }
    m *= (1.f / GG);
    float v = s2 * (1.f / GG) - m * m;
    float sc = rsqrtf(v + BN_EPS) * gamma;
    float sh = beta - m * sc;
#pragma unroll
    for (int r = 0; r < GG; r++) z[r] = fmaxf(z[r] * sc + sh, 0.f);
}

__global__ void __launch_bounds__(128) mlp_kernel(
    const float* __restrict__ A1w, const float* __restrict__ A1b,
    const float* __restrict__ Ag1, const float* __restrict__ Ab1,
    const float* __restrict__ A2w, const float* __restrict__ A2b,
    const float* __restrict__ Ag2, const float* __restrict__ Ab2,
    const float* __restrict__ A3w, const float* __restrict__ A3b,
    float* __restrict__ out)
{
    __shared__ float p_s[GG * HH];
    const int c = threadIdx.x;
    for (int idx = c; idx < GG * HH; idx += 128) p_s[idx] = g_pooled[idx];
    __syncthreads();

    float z[GG];
    mlp_layer(z, p_s, A1w + c * HH, A1b[c], Ag1[c], Ab1[c]);
    __syncthreads();
#pragma unroll
    for (int r = 0; r < GG; r++) p_s[r * HH + c] = z[r];
    __syncthreads();

    mlp_layer(z, p_s, A2w + c * HH, A2b[c], Ag2[c], Ab2[c]);
    __syncthreads();
#pragma unroll
    for (int r = 0; r < GG; r++) p_s[r * HH + c] = z[r];
    __syncthreads();

    for (int idx = c; idx < GG * AA; idx += 128) {
        int r = idx >> 4, a2 = idx & 15;
        float acc = A3b[a2];
        for (int k = 0; k < HH; k++) acc += p_s[r * HH + k] * A3w[a2 * HH + k];
        out[idx] = 1.f / (1.f + expf(-acc));
    }
}

// ---------------- host launch ----------------
extern "C" void kernel_launch(void* const* d_in, const int* in_sizes, int n_in,
                              void* d_out, int out_size) {
    int ix, iea, iei, ib;
    int iW1, ib1, iWe1, ibe1, ig1, ibt1, iW2, ib2, iWe2, ibe2, ig2, ibt2;
    int iA1w, iA1b, iAg1, iAb1, iA2w, iA2b, iAg2, iAb2, iA3w, iA3b;
    if (in_sizes[2] == 2 * EE || in_sizes[2] == 4 * EE) {
        ix = 0; iea = 1; iei = 2; ib = 3;
        iW1 = 4; ib1 = 5; iWe1 = 6; ibe1 = 7; ig1 = 8; ibt1 = 9;
        iW2 = 10; ib2 = 11; iWe2 = 12; ibe2 = 13; ig2 = 14; ibt2 = 15;
        iA1w = 16; iA1b = 17; iAg1 = 18; iAb1 = 19;
        iA2w = 20; iA2b = 21; iAg2 = 22; iAb2 = 23; iA3w = 24; iA3b = 25;
    } else {
        ix = 0; iea = 1;
        iW1 = 2; ib1 = 3; iWe1 = 4; ibe1 = 5; ig1 = 6; ibt1 = 7;
        iW2 = 8; ib2 = 9; iWe2 = 10; ibe2 = 11; ig2 = 12; ibt2 = 13;
        iA1w = 14; iA1b = 15; iAg1 = 16; iAb1 = 17;
        iA2w = 18; iA2b = 19; iAg2 = 20; iAb2 = 21; iA3w = 22; iA3b = 23;
        iei = 24; ib = 25;
    }

    const float* x   = (const float*)d_in[ix];
    const float* ea  = (const float*)d_in[iea];
    const void*  ei  = d_in[iei];
    const void*  bat = d_in[ib];
    float* out = (float*)d_out;

    const int n4 = NN * HH / 4;
    const int stream_blocks = (n4 + 1023) / 1024;    // 4 float4 per thread @ 256 thr
    const int edge_blocks = (NTILES + 63) / 64;      // 782
    const int gemm_blocks = (NN + 127) / 128;        // 391

    // launch indices: detect=0, copy=1, zero_stats=2, edge=3 (ncu-profiled slot)
    detect_kernel<<<1, 256>>>((const unsigned int*)ei);
    copy_init_kernel<<<stream_blocks, 256>>>((const float4*)x, n4);
    zero_stats_kernel<<<1, 128>>>();

    // ---- layer 1 ----
    edge_mma_kernel<<<edge_blocks, 256>>>(x, 0, ea, ei,
                                          (const float*)d_in[iWe1], (const float*)d_in[ibe1]);
    node_gemm_mma_kernel<<<gemm_blocks, 512>>>((const float*)d_in[iW1], (const float*)d_in[ib1]);
    normalize_kernel<<<stream_blocks, 256>>>(0, n4, (const float*)d_in[ig1], (const float*)d_in[ibt1]);

    // ---- layer 2 ----
    edge_mma_kernel<<<edge_blocks, 256>>>(x, 1, ea, ei,
                                          (const float*)d_in[iWe2], (const float*)d_in[ibe2]);
    node_gemm_mma_kernel<<<gemm_blocks, 512>>>((const float*)d_in[iW2], (const float*)d_in[ib2]);
    normalize_kernel<<<stream_blocks, 256>>>(1, n4, (const float*)d_in[ig2], (const float*)d_in[ibt2]);

    // ---- pool + MLP ----
    pool_kernel<<<GG, 128>>>(bat);
    mlp_kernel<<<1, 128>>>((const float*)d_in[iA1w], (const float*)d_in[iA1b],
                           (const float*)d_in[iAg1], (const float*)d_in[iAb1],
                           (const float*)d_in[iA2w], (const float*)d_in[iA2b],
                           (const float*)d_in[iAg2], (const float*)d_in[iAb2],
                           (const float*)d_in[iA3w], (const float*)d_in[iA3b], out);
}

// round 13
// speedup vs baseline: 1.0159x; 1.0159x over previous
#include <cuda_runtime.h>
#include <cuda_bf16.h>
#include <math.h>

#define NN 50000
#define EE 800000
#define HH 128
#define EDIM 32
#define GG 64
#define AA 16
#define BN_EPS 1e-5f
#define FULLM 0xffffffffu
#define TS 72   // smem tile row stride (floats): conflict-free STS.64/LDS.128

// ---------------- scratch (static device globals; no allocation) ----------------
__device__ float g_y[(size_t)NN * HH];
__device__ float g_u[(size_t)NN * HH];
__device__ float g_h[(size_t)NN * HH];
__device__ float g_sum[HH];
__device__ float g_sumsq[HH];
__device__ float g_pooled[GG * HH];
__device__ int   g_idx64;

// ---------------- int32/int64 index handling ----------------
__device__ __forceinline__ long long read_idx(const void* p, long long i, bool i64) {
    if (i64) return ((const long long*)p)[i];
    return (long long)((const int*)p)[i];
}

__global__ void detect_kernel(const unsigned int* __restrict__ w) {
    __shared__ int f;
    if (threadIdx.x == 0) f = 0;
    __syncthreads();
    int local = 0;
    for (int i = threadIdx.x * 2 + 1; i < 8192; i += 512)
        if (w[i]) local = 1;
    if (local) atomicOr(&f, 1);
    __syncthreads();
    if (threadIdx.x == 0) g_idx64 = f ? 0 : 1;
}

// ---------------- bf16 2-split helpers ----------------
__device__ __forceinline__ unsigned pack2(float e0, float e1) {
    unsigned r;
    asm("cvt.rn.bf16x2.f32 %0, %1, %2;" : "=r"(r) : "f"(e1), "f"(e0));
    return r;
}
__device__ __forceinline__ void split2(float e0, float e1, unsigned& hi, unsigned& lo) {
    hi = pack2(e0, e1);
    float f0 = __uint_as_float(hi << 16);
    float f1 = __uint_as_float(hi & 0xffff0000u);
    lo = pack2(e0 - f0, e1 - f1);
}
__device__ __forceinline__ void mma_bf16(float& c0, float& c1, float& c2, float& c3,
                                         unsigned a0, unsigned a1, unsigned a2, unsigned a3,
                                         unsigned b0, unsigned b1) {
    asm volatile("mma.sync.aligned.m16n8k16.row.col.f32.bf16.bf16.f32 "
                 "{%0,%1,%2,%3}, {%4,%5,%6,%7}, {%8,%9}, {%0,%1,%2,%3};"
                 : "+f"(c0), "+f"(c1), "+f"(c2), "+f"(c3)
                 : "r"(a0), "r"(a1), "r"(a2), "r"(a3), "r"(b0), "r"(b1));
}

// Stage pre-split B fragments for one k32 block (1024 float4).
__device__ __forceinline__ void stage_bfrag(float4* bfrag, const float* __restrict__ Wmat,
                                            int ldw, int kbase, int tid, int nthreads) {
    for (int idx = tid; idx < 1024; idx += nthreads) {
        int nt = idx >> 6, kc = (idx >> 5) & 1, ln = idx & 31;
        int g2 = ln >> 2, t2 = ln & 3;
        int c = nt * 8 + g2;
        int k0 = kbase + 16 * kc + 2 * t2;
        float w00 = Wmat[c * ldw + k0];
        float w01 = Wmat[c * ldw + k0 + 1];
        float w10 = Wmat[c * ldw + k0 + 8];
        float w11 = Wmat[c * ldw + k0 + 9];
        unsigned bh0, bl0, bh1, bl1;
        split2(w00, w01, bh0, bl0);
        split2(w10, w11, bh1, bl1);
        bfrag[idx] = make_float4(__uint_as_float(bh0), __uint_as_float(bh1),
                                 __uint_as_float(bl0), __uint_as_float(bl1));
    }
}

// Load raw A data (2 rows x one k32 block) as 8 float2.
__device__ __forceinline__ void load_a_raw(const float* __restrict__ row0,
                                           const float* __restrict__ row1,
                                           int kbase, int t, float2 A[8]) {
#pragma unroll
    for (int kc = 0; kc < 2; kc++) {
        int k0 = kbase + 16 * kc + 2 * t;
        A[kc * 4 + 0] = *(const float2*)(row0 + k0);
        A[kc * 4 + 1] = *(const float2*)(row1 + k0);
        A[kc * 4 + 2] = *(const float2*)(row0 + k0 + 8);
        A[kc * 4 + 3] = *(const float2*)(row1 + k0 + 8);
    }
}
__device__ __forceinline__ void split_a(const float2 A[8],
                                        unsigned ahi[2][4], unsigned alo[2][4]) {
#pragma unroll
    for (int kc = 0; kc < 2; kc++) {
        split2(A[kc * 4 + 0].x, A[kc * 4 + 0].y, ahi[kc][0], alo[kc][0]);
        split2(A[kc * 4 + 1].x, A[kc * 4 + 1].y, ahi[kc][1], alo[kc][1]);
        split2(A[kc * 4 + 2].x, A[kc * 4 + 2].y, ahi[kc][2], alo[kc][2]);
        split2(A[kc * 4 + 3].x, A[kc * 4 + 3].y, ahi[kc][3], alo[kc][3]);
    }
}

// ---------------- y = src (copy) + zero BN stats ----------------
__global__ void copy_init_kernel(const float4* __restrict__ src, int n4) {
    if (blockIdx.x == 0 && threadIdx.x < HH) {
        g_sum[threadIdx.x] = 0.f;
        g_sumsq[threadIdx.x] = 0.f;
    }
    int i = blockIdx.x * blockDim.x + threadIdx.x;
    if (i < n4) ((float4*)g_y)[i] = src[i];
}

// ---------------- edge kernel: mma elin + smem-tiled coalesced epilogue ----------------
#define NTILES 50000         // EE/16
#define WTILES 8
__global__ void __launch_bounds__(256, 2) edge_mma_kernel(
    const float* __restrict__ xin_ext, int use_h,
    const float* __restrict__ ea,
    const void* __restrict__ eiv,
    const float* __restrict__ We,   // [128][32] row-major
    const float* __restrict__ be)
{
    __shared__ float4 bfrag[1024];        // 16KB
    __shared__ float be_s[HH];
    __shared__ float sbuf[8][16 * TS];    // per-warp [16 edges][64 cols padded]  36.9KB

    const int tid = threadIdx.x;
    // layer 2: re-zero BN stats for the upcoming gemm (edge2 strictly precedes gemm2,
    // and normalize1 — the last reader of the old stats — precedes edge2)
    if (use_h && blockIdx.x == 0 && tid < HH) {
        g_sum[tid] = 0.f;
        g_sumsq[tid] = 0.f;
    }
    stage_bfrag(bfrag, We, EDIM, 0, tid, 256);
    if (tid < HH) be_s[tid] = be[tid];
    __syncthreads();

    const float* __restrict__ xin = use_h ? g_h : xin_ext;
    const int lane = tid & 31, warp = tid >> 5;
    const int g = lane >> 2, t = lane & 3;
    const bool i64 = (g_idx64 != 0);
    const int half16 = lane >> 4;        // 0/1: which of 2 edges per epilogue iter
    const int li = lane & 15;            // column quad within edge half-row
    float* buf = sbuf[warp];
    const int base = (blockIdx.x * 8 + warp) * WTILES;

    int nt_here = NTILES - base;
    if (nt_here <= 0) return;
    if (nt_here > WTILES) nt_here = WTILES;

    for (int it = 0; it < nt_here; it++) {
        long long e0 = (long long)(base + it) * 16;
        int svC = 0, dvC = 0;
        if (lane < 16) {
            svC = (int)read_idx(eiv, e0 + lane, i64);
            dvC = (int)read_idx(eiv, (long long)EE + e0 + lane, i64);
        }
        float2 Ac[8];
        load_a_raw(ea + (size_t)(e0 + g) * EDIM, ea + (size_t)(e0 + g + 8) * EDIM, 0, t, Ac);

        unsigned ahi[2][4], alo[2][4];
        split_a(Ac, ahi, alo);

#pragma unroll
        for (int h = 0; h < 2; h++) {
            // ---- phase A: mma for cols [h*64, h*64+64), write to smem tile ----
#pragma unroll
            for (int ntl = 0; ntl < 8; ntl++) {
                int nt = h * 8 + ntl;
                float2 b2 = *(const float2*)(be_s + nt * 8 + 2 * t);
                float c0 = b2.x, c1 = b2.y, c2 = b2.x, c3 = b2.y;
#pragma unroll
                for (int kc = 0; kc < 2; kc++) {
                    float4 bf = bfrag[(nt * 2 + kc) * 32 + lane];
                    unsigned bh0 = __float_as_uint(bf.x), bh1 = __float_as_uint(bf.y);
                    unsigned bl0 = __float_as_uint(bf.z), bl1 = __float_as_uint(bf.w);
                    mma_bf16(c0, c1, c2, c3, ahi[kc][0], ahi[kc][1], ahi[kc][2], ahi[kc][3], bh0, bh1);
                    mma_bf16(c0, c1, c2, c3, alo[kc][0], alo[kc][1], alo[kc][2], alo[kc][3], bh0, bh1);
                    mma_bf16(c0, c1, c2, c3, ahi[kc][0], ahi[kc][1], ahi[kc][2], ahi[kc][3], bl0, bl1);
                }
                int cw = ntl * 8 + 2 * t;
                *(float2*)(buf + g * TS + cw)       = make_float2(c0, c1);
                *(float2*)(buf + (g + 8) * TS + cw) = make_float2(c2, c3);
            }
            __syncwarp();

            // ---- phase B: coalesced gather + relu + red, 2 edges x 64 cols per iter ----
#pragma unroll
            for (int g2 = 0; g2 < 4; g2++) {
                float4 m0, m1, xv0, xv1;
                int e0i = 4 * g2 + half16;       // edges e0i and e0i+2
                int e1i = e0i + 2;
                int s0 = __shfl_sync(FULLM, svC, e0i);
                int s1 = __shfl_sync(FULLM, svC, e1i);
                m0 = *(const float4*)(buf + e0i * TS + 4 * li);
                m1 = *(const float4*)(buf + e1i * TS + 4 * li);
                xv0 = *(const float4*)(xin + (size_t)s0 * HH + h * 64 + 4 * li);
                xv1 = *(const float4*)(xin + (size_t)s1 * HH + h * 64 + 4 * li);
                int d0 = __shfl_sync(FULLM, dvC, e0i);
                int d1 = __shfl_sync(FULLM, dvC, e1i);
                {
                    float o0 = fmaxf(m0.x + xv0.x, 0.f);
                    float o1 = fmaxf(m0.y + xv0.y, 0.f);
                    float o2 = fmaxf(m0.z + xv0.z, 0.f);
                    float o3 = fmaxf(m0.w + xv0.w, 0.f);
                    asm volatile("red.global.add.v4.f32 [%0], {%1,%2,%3,%4};"
                                 :: "l"(g_y + (size_t)d0 * HH + h * 64 + 4 * li),
                                    "f"(o0), "f"(o1), "f"(o2), "f"(o3) : "memory");
                }
                {
                    float o0 = fmaxf(m1.x + xv1.x, 0.f);
                    float o1 = fmaxf(m1.y + xv1.y, 0.f);
                    float o2 = fmaxf(m1.z + xv1.z, 0.f);
                    float o3 = fmaxf(m1.w + xv1.w, 0.f);
                    asm volatile("red.global.add.v4.f32 [%0], {%1,%2,%3,%4};"
                                 :: "l"(g_y + (size_t)d1 * HH + h * 64 + 4 * li),
                                    "f"(o0), "f"(o1), "f"(o2), "f"(o3) : "memory");
                }
            }
            __syncwarp();
        }
    }
}

// ---------------- node GEMM + fused BN sums (smem-staged): u = g_y @ W.T + b ----------------
// 512 threads, 16 warps. Warp: 16 rows x 64 cols. Block: 128 rows x 128 cols.
__global__ void __launch_bounds__(512) node_gemm_mma_kernel(
    const float* __restrict__ W,
    const float* __restrict__ b)
{
    __shared__ float4 bfrag[1024];   // restaged per k32 block, 16KB
    __shared__ float b_s[HH];
    __shared__ float s_sum[HH], s_sumsq[HH];

    const int tid = threadIdx.x;
    const int lane = tid & 31, warp = tid >> 5;
    const int g = lane >> 2, t = lane & 3;
    const int colhalf = warp >> 3;
    const int rw = warp & 7;
    const int nt0 = colhalf * 8;
    const int rowbase = blockIdx.x * 128 + rw * 16;
    const bool active = (rowbase < NN);      // NN % 16 == 0
    const bool even = ((t & 1) == 0);
    const int cboff = (t & 2) ? 4 : 0;

    if (tid < HH) {
        b_s[tid] = b[tid];
        s_sum[tid] = 0.f;
        s_sumsq[tid] = 0.f;
    }

    float C[8][4];
#pragma unroll
    for (int nt = 0; nt < 8; nt++)
#pragma unroll
        for (int q = 0; q < 4; q++) C[nt][q] = 0.f;

    for (int kb = 0; kb < 4; kb++) {
        __syncthreads();
        stage_bfrag(bfrag, W, HH, kb * 32, tid, 512);
        __syncthreads();

        if (active) {
            const float* row0 = g_y + (size_t)(rowbase + g) * HH;
            const float* row1 = g_y + (size_t)(rowbase + g + 8) * HH;
            float2 A[8];
            load_a_raw(row0, row1, kb * 32, t, A);
            unsigned ahi[2][4], alo[2][4];
            split_a(A, ahi, alo);

#pragma unroll
            for (int ntl = 0; ntl < 8; ntl++) {
                int nt = nt0 + ntl;
#pragma unroll
                for (int kc = 0; kc < 2; kc++) {
                    float4 bf = bfrag[(nt * 2 + kc) * 32 + lane];
                    unsigned bh0 = __float_as_uint(bf.x), bh1 = __float_as_uint(bf.y);
                    unsigned bl0 = __float_as_uint(bf.z), bl1 = __float_as_uint(bf.w);
                    mma_bf16(C[ntl][0], C[ntl][1], C[ntl][2], C[ntl][3],
                             ahi[kc][0], ahi[kc][1], ahi[kc][2], ahi[kc][3], bh0, bh1);
                    mma_bf16(C[ntl][0], C[ntl][1], C[ntl][2], C[ntl][3],
                             alo[kc][0], alo[kc][1], alo[kc][2], alo[kc][3], bh0, bh1);
                    mma_bf16(C[ntl][0], C[ntl][1], C[ntl][2], C[ntl][3],
                             ahi[kc][0], ahi[kc][1], ahi[kc][2], ahi[kc][3], bl0, bl1);
                }
            }
        }
    }

    if (active) {
        const int orow = rowbase + (even ? g : g + 8);
        float* outp = g_u + (size_t)orow * HH + cboff;
#pragma unroll
        for (int ntl = 0; ntl < 8; ntl++) {
            int nt = nt0 + ntl;
            float c0 = C[ntl][0] + b_s[nt * 8 + 2 * t];
            float c1 = C[ntl][1] + b_s[nt * 8 + 2 * t + 1];
            float c2 = C[ntl][2] + b_s[nt * 8 + 2 * t];
            float c3 = C[ntl][3] + b_s[nt * 8 + 2 * t + 1];

            // ---- BN column sums over this warp's 16 rows -> smem staging ----
            float s0 = c0 + c2, s1 = c1 + c3;
            float q0 = c0 * c0 + c2 * c2, q1 = c1 * c1 + c3 * c3;
#pragma unroll
            for (int m = 4; m <= 16; m <<= 1) {
                s0 += __shfl_xor_sync(FULLM, s0, m);
                s1 += __shfl_xor_sync(FULLM, s1, m);
                q0 += __shfl_xor_sync(FULLM, q0, m);
                q1 += __shfl_xor_sync(FULLM, q1, m);
            }
            if (g == 0) {   // lanes 0-3: one contribution per column pair
                int col = nt * 8 + 2 * t;
                atomicAdd(&s_sum[col], s0);
                atomicAdd(&s_sum[col + 1], s1);
                atomicAdd(&s_sumsq[col], q0);
                atomicAdd(&s_sumsq[col + 1], q1);
            }

            float e0 = even ? c2 : c0;
            float e1 = even ? c3 : c1;
            float r0 = __shfl_xor_sync(FULLM, e0, 1);
            float r1 = __shfl_xor_sync(FULLM, e1, 1);
            float4 o;
            if (even) { o = make_float4(c0, c1, r0, r1); }
            else      { o = make_float4(r0, r1, c2, c3); }
            *(float4*)(outp + nt * 8) = o;
        }
    }

    // ---- flush block sums: 128 global atomics per block ----
    __syncthreads();
    if (tid < HH) {
        atomicAdd(&g_sum[tid], s_sum[tid]);
        atomicAdd(&g_sumsq[tid], s_sumsq[tid]);
    }
}

// ---------------- normalize (stats computed in-block): h = act(u*scale+shift) ----------------
__global__ void normalize_kernel(int mode, int n4,
                                 const float* __restrict__ gamma,
                                 const float* __restrict__ beta) {
    __shared__ float sc_s[HH], sh_s[HH];
    if (threadIdx.x < HH) {
        int c = threadIdx.x;
        float m = g_sum[c] * (1.f / NN);
        float v = g_sumsq[c] * (1.f / NN) - m * m;
        float rs = rsqrtf(v + BN_EPS);
        float sc = rs * gamma[c];
        sc_s[c] = sc;
        sh_s[c] = beta[c] - m * sc;
    }
    __syncthreads();

    int i = blockIdx.x * blockDim.x + threadIdx.x;
    if (i >= n4) return;
    int c0 = (i * 4) & 127;
    float4 sc = *(const float4*)(sc_s + c0);
    float4 sh = *(const float4*)(sh_s + c0);
    float4 v = ((const float4*)g_u)[i];
    v.x = fmaxf(v.x * sc.x + sh.x, 0.f);
    v.y = fmaxf(v.y * sc.y + sh.y, 0.f);
    v.z = fmaxf(v.z * sc.z + sh.z, 0.f);
    v.w = fmaxf(v.w * sc.w + sh.w, 0.f);
    if (mode == 1) {
        v.x = 1.f / (1.f + expf(-v.x));
        v.y = 1.f / (1.f + expf(-v.y));
        v.z = 1.f / (1.f + expf(-v.z));
        v.w = 1.f / (1.f + expf(-v.w));
    }
    ((float4*)g_h)[i] = v;
    if (mode == 0) ((float4*)g_y)[i] = v;   // layer2 accumulator init
}

// ---------------- per-graph mean pooling ----------------
__device__ __forceinline__ int lb_search(const void* bp, int target, bool i64) {
    int l = 0, r = NN;
    while (l < r) {
        int m = (l + r) >> 1;
        if (read_idx(bp, m, i64) < (long long)target) l = m + 1; else r = m;
    }
    return l;
}

__global__ void pool_kernel(const void* __restrict__ batchv) {
    const int g = blockIdx.x, c = threadIdx.x;
    const bool i64 = (g_idx64 != 0);
    int lo = lb_search(batchv, g, i64);
    int hi = lb_search(batchv, g + 1, i64);
    float s = 0.f;
    for (int i = lo; i < hi; i++) s += g_h[(size_t)i * HH + c];
    int cnt = hi - lo;
    g_pooled[g * HH + c] = s / fmaxf((float)cnt, 1.f);
}

// ---------------- fused action MLP ----------------
__device__ __forceinline__ void mlp_layer(float* z, const float* p_s,
                                          const float* __restrict__ Wrow,
                                          float bias, float gamma, float beta) {
#pragma unroll
    for (int r = 0; r < GG; r++) z[r] = bias;
    for (int k = 0; k < HH; k += 4) {
        float4 w = *(const float4*)(Wrow + k);
#pragma unroll
        for (int r = 0; r < GG; r++) {
            float4 p = *(const float4*)(p_s + r * HH + k);
            z[r] += w.x * p.x + w.y * p.y + w.z * p.z + w.w * p.w;
        }
    }
    float m = 0.f, s2 = 0.f;
#pragma unroll
    for (int r = 0; r < GG; r++) { m += z[r]; s2 += z[r] * z[r]; }
    m *= (1.f / GG);
    float v = s2 * (1.f / GG) - m * m;
    float sc = rsqrtf(v + BN_EPS) * gamma;
    float sh = beta - m * sc;
#pragma unroll
    for (int r = 0; r < GG; r++) z[r] = fmaxf(z[r] * sc + sh, 0.f);
}

__global__ void __launch_bounds__(128) mlp_kernel(
    const float* __restrict__ A1w, const float* __restrict__ A1b,
    const float* __restrict__ Ag1, const float* __restrict__ Ab1,
    const float* __restrict__ A2w, const float* __restrict__ A2b,
    const float* __restrict__ Ag2, const float* __restrict__ Ab2,
    const float* __restrict__ A3w, const float* __restrict__ A3b,
    float* __restrict__ out)
{
    __shared__ float p_s[GG * HH];
    const int c = threadIdx.x;
    for (int idx = c; idx < GG * HH; idx += 128) p_s[idx] = g_pooled[idx];
    __syncthreads();

    float z[GG];
    mlp_layer(z, p_s, A1w + c * HH, A1b[c], Ag1[c], Ab1[c]);
    __syncthreads();
#pragma unroll
    for (int r = 0; r < GG; r++) p_s[r * HH + c] = z[r];
    __syncthreads();

    mlp_layer(z, p_s, A2w + c * HH, A2b[c], Ag2[c], Ab2[c]);
    __syncthreads();
#pragma unroll
    for (int r = 0; r < GG; r++) p_s[r * HH + c] = z[r];
    __syncthreads();

    for (int idx = c; idx < GG * AA; idx += 128) {
        int r = idx >> 4, a2 = idx & 15;
        float acc = A3b[a2];
        for (int k = 0; k < HH; k++) acc += p_s[r * HH + k] * A3w[a2 * HH + k];
        out[idx] = 1.f / (1.f + expf(-acc));
    }
}

// ---------------- host launch ----------------
extern "C" void kernel_launch(void* const* d_in, const int* in_sizes, int n_in,
                              void* d_out, int out_size) {
    int ix, iea, iei, ib;
    int iW1, ib1, iWe1, ibe1, ig1, ibt1, iW2, ib2, iWe2, ibe2, ig2, ibt2;
    int iA1w, iA1b, iAg1, iAb1, iA2w, iA2b, iAg2, iAb2, iA3w, iA3b;
    if (in_sizes[2] == 2 * EE || in_sizes[2] == 4 * EE) {
        ix = 0; iea = 1; iei = 2; ib = 3;
        iW1 = 4; ib1 = 5; iWe1 = 6; ibe1 = 7; ig1 = 8; ibt1 = 9;
        iW2 = 10; ib2 = 11; iWe2 = 12; ibe2 = 13; ig2 = 14; ibt2 = 15;
        iA1w = 16; iA1b = 17; iAg1 = 18; iAb1 = 19;
        iA2w = 20; iA2b = 21; iAg2 = 22; iAb2 = 23; iA3w = 24; iA3b = 25;
    } else {
        ix = 0; iea = 1;
        iW1 = 2; ib1 = 3; iWe1 = 4; ibe1 = 5; ig1 = 6; ibt1 = 7;
        iW2 = 8; ib2 = 9; iWe2 = 10; ibe2 = 11; ig2 = 12; ibt2 = 13;
        iA1w = 14; iA1b = 15; iAg1 = 16; iAb1 = 17;
        iA2w = 18; iA2b = 19; iAg2 = 20; iAb2 = 21; iA3w = 22; iA3b = 23;
        iei = 24; ib = 25;
    }

    const float* x   = (const float*)d_in[ix];
    const float* ea  = (const float*)d_in[iea];
    const void*  ei  = d_in[iei];
    const void*  bat = d_in[ib];
    float* out = (float*)d_out;

    const int n4 = NN * HH / 4;
    const int copy_blocks = (n4 + 255) / 256;
    const int edge_blocks = (NTILES + 63) / 64;      // 782
    const int gemm_blocks = (NN + 127) / 128;        // 391

    // launch indices: detect=0, copy=1, edge1=2, gemm1=3 (ncu-profiled slot)
    detect_kernel<<<1, 256>>>((const unsigned int*)ei);
    copy_init_kernel<<<copy_blocks, 256>>>((const float4*)x, n4);

    // ---- layer 1 ----
    edge_mma_kernel<<<edge_blocks, 256>>>(x, 0, ea, ei,
                                          (const float*)d_in[iWe1], (const float*)d_in[ibe1]);
    node_gemm_mma_kernel<<<gemm_blocks, 512>>>((const float*)d_in[iW1], (const float*)d_in[ib1]);
    normalize_kernel<<<copy_blocks, 256>>>(0, n4, (const float*)d_in[ig1], (const float*)d_in[ibt1]);

    // ---- layer 2 ----
    edge_mma_kernel<<<edge_blocks, 256>>>(x, 1, ea, ei,
                                          (const float*)d_in[iWe2], (const float*)d_in[ibe2]);
    node_gemm_mma_kernel<<<gemm_blocks, 512>>>((const float*)d_in[iW2], (const float*)d_in[ib2]);
    normalize_kernel<<<copy_blocks, 256>>>(1, n4, (const float*)d_in[ig2], (const float*)d_in[ibt2]);

    // ---- pool + MLP ----
    pool_kernel<<<GG, 128>>>(bat);
    mlp_kernel<<<1, 128>>>((const float*)d_in[iA1w], (const float*)d_in[iA1b],
                           (const float*)d_in[iAg1], (const float*)d_in[iAb1],
                           (const float*)d_in[iA2w], (const float*)d_in[iA2b],
                           (const float*)d_in[iAg2], (const float*)d_in[iAb2],
                           (const float*)d_in[iA3w], (const float*)d_in[iA3b], out);
}

// round 14
// speedup vs baseline: 1.0313x; 1.0152x over previous
#include <cuda_runtime.h>
#include <cuda_bf16.h>
#include <math.h>

#define NN 50000
#define EE 800000
#define HH 128
#define EDIM 32
#define GG 64
#define AA 16
#define BN_EPS 1e-5f
#define FULLM 0xffffffffu
#define TS 72   // smem tile row stride (floats): conflict-free STS.64/LDS.128

// ---------------- scratch (static device globals; no allocation) ----------------
__device__ float g_y[(size_t)NN * HH];
__device__ float g_u[(size_t)NN * HH];
__device__ float g_h[(size_t)NN * HH];
__device__ float g_sum[HH];
__device__ float g_sumsq[HH];
__device__ float g_pooled[GG * HH];
__device__ int   g_idx64;

// ---------------- int32/int64 index handling ----------------
__device__ __forceinline__ long long read_idx(const void* p, long long i, bool i64) {
    if (i64) return ((const long long*)p)[i];
    return (long long)((const int*)p)[i];
}

__global__ void detect_kernel(const unsigned int* __restrict__ w) {
    __shared__ int f;
    if (threadIdx.x == 0) f = 0;
    __syncthreads();
    int local = 0;
    for (int i = threadIdx.x * 2 + 1; i < 8192; i += 512)
        if (w[i]) local = 1;
    if (local) atomicOr(&f, 1);
    __syncthreads();
    if (threadIdx.x == 0) g_idx64 = f ? 0 : 1;
}

// ---------------- bf16 2-split helpers ----------------
__device__ __forceinline__ unsigned pack2(float e0, float e1) {
    unsigned r;
    asm("cvt.rn.bf16x2.f32 %0, %1, %2;" : "=r"(r) : "f"(e1), "f"(e0));
    return r;
}
__device__ __forceinline__ void split2(float e0, float e1, unsigned& hi, unsigned& lo) {
    hi = pack2(e0, e1);
    float f0 = __uint_as_float(hi << 16);
    float f1 = __uint_as_float(hi & 0xffff0000u);
    lo = pack2(e0 - f0, e1 - f1);
}
__device__ __forceinline__ void mma_bf16(float& c0, float& c1, float& c2, float& c3,
                                         unsigned a0, unsigned a1, unsigned a2, unsigned a3,
                                         unsigned b0, unsigned b1) {
    asm volatile("mma.sync.aligned.m16n8k16.row.col.f32.bf16.bf16.f32 "
                 "{%0,%1,%2,%3}, {%4,%5,%6,%7}, {%8,%9}, {%0,%1,%2,%3};"
                 : "+f"(c0), "+f"(c1), "+f"(c2), "+f"(c3)
                 : "r"(a0), "r"(a1), "r"(a2), "r"(a3), "r"(b0), "r"(b1));
}

// Stage pre-split B fragments for one k32 block (1024 float4).
__device__ __forceinline__ void stage_bfrag(float4* bfrag, const float* __restrict__ Wmat,
                                            int ldw, int kbase, int tid, int nthreads) {
    for (int idx = tid; idx < 1024; idx += nthreads) {
        int nt = idx >> 6, kc = (idx >> 5) & 1, ln = idx & 31;
        int g2 = ln >> 2, t2 = ln & 3;
        int c = nt * 8 + g2;
        int k0 = kbase + 16 * kc + 2 * t2;
        float w00 = Wmat[c * ldw + k0];
        float w01 = Wmat[c * ldw + k0 + 1];
        float w10 = Wmat[c * ldw + k0 + 8];
        float w11 = Wmat[c * ldw + k0 + 9];
        unsigned bh0, bl0, bh1, bl1;
        split2(w00, w01, bh0, bl0);
        split2(w10, w11, bh1, bl1);
        bfrag[idx] = make_float4(__uint_as_float(bh0), __uint_as_float(bh1),
                                 __uint_as_float(bl0), __uint_as_float(bl1));
    }
}

// Load raw A data (2 rows x one k32 block) as 8 float2.
__device__ __forceinline__ void load_a_raw(const float* __restrict__ row0,
                                           const float* __restrict__ row1,
                                           int kbase, int t, float2 A[8]) {
#pragma unroll
    for (int kc = 0; kc < 2; kc++) {
        int k0 = kbase + 16 * kc + 2 * t;
        A[kc * 4 + 0] = *(const float2*)(row0 + k0);
        A[kc * 4 + 1] = *(const float2*)(row1 + k0);
        A[kc * 4 + 2] = *(const float2*)(row0 + k0 + 8);
        A[kc * 4 + 3] = *(const float2*)(row1 + k0 + 8);
    }
}
__device__ __forceinline__ void split_a(const float2 A[8],
                                        unsigned ahi[2][4], unsigned alo[2][4]) {
#pragma unroll
    for (int kc = 0; kc < 2; kc++) {
        split2(A[kc * 4 + 0].x, A[kc * 4 + 0].y, ahi[kc][0], alo[kc][0]);
        split2(A[kc * 4 + 1].x, A[kc * 4 + 1].y, ahi[kc][1], alo[kc][1]);
        split2(A[kc * 4 + 2].x, A[kc * 4 + 2].y, ahi[kc][2], alo[kc][2]);
        split2(A[kc * 4 + 3].x, A[kc * 4 + 3].y, ahi[kc][3], alo[kc][3]);
    }
}

// ---------------- y = src (copy) + zero BN stats ----------------
__global__ void copy_init_kernel(const float4* __restrict__ src, int n4) {
    if (blockIdx.x == 0 && threadIdx.x < HH) {
        g_sum[threadIdx.x] = 0.f;
        g_sumsq[threadIdx.x] = 0.f;
    }
    int i = blockIdx.x * blockDim.x + threadIdx.x;
    if (i < n4) ((float4*)g_y)[i] = src[i];
}

// ---------------- edge kernel: mma elin + smem-tiled coalesced epilogue ----------------
#define NTILES 50000         // EE/16
#define WTILES 8
__global__ void __launch_bounds__(256, 2) edge_mma_kernel(
    const float* __restrict__ xin_ext, int use_h,
    const float* __restrict__ ea,
    const void* __restrict__ eiv,
    const float* __restrict__ We,   // [128][32] row-major
    const float* __restrict__ be)
{
    __shared__ float4 bfrag[1024];        // 16KB
    __shared__ float be_s[HH];
    __shared__ float sbuf[8][16 * TS];    // per-warp [16 edges][64 cols padded]  36.9KB

    const int tid = threadIdx.x;
    // layer 2: re-zero BN stats for the upcoming gemm (edge2 strictly precedes gemm2,
    // and normalize1 — the last reader of the old stats — precedes edge2)
    if (use_h && blockIdx.x == 0 && tid < HH) {
        g_sum[tid] = 0.f;
        g_sumsq[tid] = 0.f;
    }
    stage_bfrag(bfrag, We, EDIM, 0, tid, 256);
    if (tid < HH) be_s[tid] = be[tid];
    __syncthreads();

    const float* __restrict__ xin = use_h ? g_h : xin_ext;
    const int lane = tid & 31, warp = tid >> 5;
    const int g = lane >> 2, t = lane & 3;
    const bool i64 = (g_idx64 != 0);
    const int half16 = lane >> 4;        // 0/1: which of 2 edges per epilogue iter
    const int li = lane & 15;            // column quad within edge half-row
    float* buf = sbuf[warp];
    const int base = (blockIdx.x * 8 + warp) * WTILES;

    int nt_here = NTILES - base;
    if (nt_here <= 0) return;
    if (nt_here > WTILES) nt_here = WTILES;

    for (int it = 0; it < nt_here; it++) {
        long long e0 = (long long)(base + it) * 16;
        int svC = 0, dvC = 0;
        if (lane < 16) {
            svC = (int)read_idx(eiv, e0 + lane, i64);
            dvC = (int)read_idx(eiv, (long long)EE + e0 + lane, i64);
        }
        float2 Ac[8];
        load_a_raw(ea + (size_t)(e0 + g) * EDIM, ea + (size_t)(e0 + g + 8) * EDIM, 0, t, Ac);

        unsigned ahi[2][4], alo[2][4];
        split_a(Ac, ahi, alo);

#pragma unroll
        for (int h = 0; h < 2; h++) {
            // ---- phase A: mma for cols [h*64, h*64+64), write to smem tile ----
#pragma unroll
            for (int ntl = 0; ntl < 8; ntl++) {
                int nt = h * 8 + ntl;
                float2 b2 = *(const float2*)(be_s + nt * 8 + 2 * t);
                float c0 = b2.x, c1 = b2.y, c2 = b2.x, c3 = b2.y;
#pragma unroll
                for (int kc = 0; kc < 2; kc++) {
                    float4 bf = bfrag[(nt * 2 + kc) * 32 + lane];
                    unsigned bh0 = __float_as_uint(bf.x), bh1 = __float_as_uint(bf.y);
                    unsigned bl0 = __float_as_uint(bf.z), bl1 = __float_as_uint(bf.w);
                    mma_bf16(c0, c1, c2, c3, ahi[kc][0], ahi[kc][1], ahi[kc][2], ahi[kc][3], bh0, bh1);
                    mma_bf16(c0, c1, c2, c3, alo[kc][0], alo[kc][1], alo[kc][2], alo[kc][3], bh0, bh1);
                    mma_bf16(c0, c1, c2, c3, ahi[kc][0], ahi[kc][1], ahi[kc][2], ahi[kc][3], bl0, bl1);
                }
                int cw = ntl * 8 + 2 * t;
                *(float2*)(buf + g * TS + cw)       = make_float2(c0, c1);
                *(float2*)(buf + (g + 8) * TS + cw) = make_float2(c2, c3);
            }
            __syncwarp();

            // ---- phase B: coalesced gather + relu + red, 2 edges x 64 cols per iter ----
#pragma unroll
            for (int g2 = 0; g2 < 4; g2++) {
                float4 m0, m1, xv0, xv1;
                int e0i = 4 * g2 + half16;       // edges e0i and e0i+2
                int e1i = e0i + 2;
                int s0 = __shfl_sync(FULLM, svC, e0i);
                int s1 = __shfl_sync(FULLM, svC, e1i);
                m0 = *(const float4*)(buf + e0i * TS + 4 * li);
                m1 = *(const float4*)(buf + e1i * TS + 4 * li);
                xv0 = *(const float4*)(xin + (size_t)s0 * HH + h * 64 + 4 * li);
                xv1 = *(const float4*)(xin + (size_t)s1 * HH + h * 64 + 4 * li);
                int d0 = __shfl_sync(FULLM, dvC, e0i);
                int d1 = __shfl_sync(FULLM, dvC, e1i);
                {
                    float o0 = fmaxf(m0.x + xv0.x, 0.f);
                    float o1 = fmaxf(m0.y + xv0.y, 0.f);
                    float o2 = fmaxf(m0.z + xv0.z, 0.f);
                    float o3 = fmaxf(m0.w + xv0.w, 0.f);
                    asm volatile("red.global.add.v4.f32 [%0], {%1,%2,%3,%4};"
                                 :: "l"(g_y + (size_t)d0 * HH + h * 64 + 4 * li),
                                    "f"(o0), "f"(o1), "f"(o2), "f"(o3) : "memory");
                }
                {
                    float o0 = fmaxf(m1.x + xv1.x, 0.f);
                    float o1 = fmaxf(m1.y + xv1.y, 0.f);
                    float o2 = fmaxf(m1.z + xv1.z, 0.f);
                    float o3 = fmaxf(m1.w + xv1.w, 0.f);
                    asm volatile("red.global.add.v4.f32 [%0], {%1,%2,%3,%4};"
                                 :: "l"(g_y + (size_t)d1 * HH + h * 64 + 4 * li),
                                    "f"(o0), "f"(o1), "f"(o2), "f"(o3) : "memory");
                }
            }
            __syncwarp();
        }
    }
}

// ---------------- node GEMM + fused BN sums, double-buffered B staging ----------------
// 512 threads, 16 warps. Warp: 16 rows x 64 cols. Block: 128 rows x 128 cols.
__global__ void __launch_bounds__(512) node_gemm_mma_kernel(
    const float* __restrict__ W,
    const float* __restrict__ b)
{
    __shared__ float4 bfrag[2][1024];   // double-buffered, 32KB
    __shared__ float b_s[HH];
    __shared__ float s_sum[HH], s_sumsq[HH];

    const int tid = threadIdx.x;
    const int lane = tid & 31, warp = tid >> 5;
    const int g = lane >> 2, t = lane & 3;
    const int colhalf = warp >> 3;
    const int rw = warp & 7;
    const int nt0 = colhalf * 8;
    const int rowbase = blockIdx.x * 128 + rw * 16;
    const bool active = (rowbase < NN);      // NN % 16 == 0
    const bool even = ((t & 1) == 0);
    const int cboff = (t & 2) ? 4 : 0;

    if (tid < HH) {
        b_s[tid] = b[tid];
        s_sum[tid] = 0.f;
        s_sumsq[tid] = 0.f;
    }

    float C[8][4];
#pragma unroll
    for (int nt = 0; nt < 8; nt++)
#pragma unroll
        for (int q = 0; q < 4; q++) C[nt][q] = 0.f;

    const float* row0 = g_y + (size_t)(rowbase + g) * HH;
    const float* row1 = g_y + (size_t)(rowbase + g + 8) * HH;

    stage_bfrag(bfrag[0], W, HH, 0, tid, 512);
    __syncthreads();

#pragma unroll
    for (int kb = 0; kb < 4; kb++) {
        // stage next k-block into the other buffer (overlaps with mma below)
        if (kb + 1 < 4)
            stage_bfrag(bfrag[(kb + 1) & 1], W, HH, (kb + 1) * 32, tid, 512);

        if (active) {
            const float4* bcur = bfrag[kb & 1];
            float2 A[8];
            load_a_raw(row0, row1, kb * 32, t, A);
            unsigned ahi[2][4], alo[2][4];
            split_a(A, ahi, alo);

#pragma unroll
            for (int ntl = 0; ntl < 8; ntl++) {
                int nt = nt0 + ntl;
#pragma unroll
                for (int kc = 0; kc < 2; kc++) {
                    float4 bf = bcur[(nt * 2 + kc) * 32 + lane];
                    unsigned bh0 = __float_as_uint(bf.x), bh1 = __float_as_uint(bf.y);
                    unsigned bl0 = __float_as_uint(bf.z), bl1 = __float_as_uint(bf.w);
                    mma_bf16(C[ntl][0], C[ntl][1], C[ntl][2], C[ntl][3],
                             ahi[kc][0], ahi[kc][1], ahi[kc][2], ahi[kc][3], bh0, bh1);
                    mma_bf16(C[ntl][0], C[ntl][1], C[ntl][2], C[ntl][3],
                             alo[kc][0], alo[kc][1], alo[kc][2], alo[kc][3], bh0, bh1);
                    mma_bf16(C[ntl][0], C[ntl][1], C[ntl][2], C[ntl][3],
                             ahi[kc][0], ahi[kc][1], ahi[kc][2], ahi[kc][3], bl0, bl1);
                }
            }
        }
        __syncthreads();   // staging of kb+1 done; all reads of bfrag[kb&1] done
    }

    if (active) {
        const int orow = rowbase + (even ? g : g + 8);
        float* outp = g_u + (size_t)orow * HH + cboff;
#pragma unroll
        for (int ntl = 0; ntl < 8; ntl++) {
            int nt = nt0 + ntl;
            float c0 = C[ntl][0] + b_s[nt * 8 + 2 * t];
            float c1 = C[ntl][1] + b_s[nt * 8 + 2 * t + 1];
            float c2 = C[ntl][2] + b_s[nt * 8 + 2 * t];
            float c3 = C[ntl][3] + b_s[nt * 8 + 2 * t + 1];

            // ---- BN column sums over this warp's 16 rows -> smem staging ----
            float s0 = c0 + c2, s1 = c1 + c3;
            float q0 = c0 * c0 + c2 * c2, q1 = c1 * c1 + c3 * c3;
#pragma unroll
            for (int m = 4; m <= 16; m <<= 1) {
                s0 += __shfl_xor_sync(FULLM, s0, m);
                s1 += __shfl_xor_sync(FULLM, s1, m);
                q0 += __shfl_xor_sync(FULLM, q0, m);
                q1 += __shfl_xor_sync(FULLM, q1, m);
            }
            if (g == 0) {   // lanes 0-3: one contribution per column pair
                int col = nt * 8 + 2 * t;
                atomicAdd(&s_sum[col], s0);
                atomicAdd(&s_sum[col + 1], s1);
                atomicAdd(&s_sumsq[col], q0);
                atomicAdd(&s_sumsq[col + 1], q1);
            }

            float e0 = even ? c2 : c0;
            float e1 = even ? c3 : c1;
            float r0 = __shfl_xor_sync(FULLM, e0, 1);
            float r1 = __shfl_xor_sync(FULLM, e1, 1);
            float4 o;
            if (even) { o = make_float4(c0, c1, r0, r1); }
            else      { o = make_float4(r0, r1, c2, c3); }
            *(float4*)(outp + nt * 8) = o;
        }
    }

    // ---- flush block sums: 128 global atomics per block ----
    __syncthreads();
    if (tid < HH) {
        atomicAdd(&g_sum[tid], s_sum[tid]);
        atomicAdd(&g_sumsq[tid], s_sumsq[tid]);
    }
}

// ---------------- normalize (stats computed in-block): h = act(u*scale+shift) ----------------
__global__ void normalize_kernel(int mode, int n4,
                                 const float* __restrict__ gamma,
                                 const float* __restrict__ beta) {
    __shared__ float sc_s[HH], sh_s[HH];
    if (threadIdx.x < HH) {
        int c = threadIdx.x;
        float m = g_sum[c] * (1.f / NN);
        float v = g_sumsq[c] * (1.f / NN) - m * m;
        float rs = rsqrtf(v + BN_EPS);
        float sc = rs * gamma[c];
        sc_s[c] = sc;
        sh_s[c] = beta[c] - m * sc;
    }
    __syncthreads();

    int i = blockIdx.x * blockDim.x + threadIdx.x;
    if (i >= n4) return;
    int c0 = (i * 4) & 127;
    float4 sc = *(const float4*)(sc_s + c0);
    float4 sh = *(const float4*)(sh_s + c0);
    float4 v = ((const float4*)g_u)[i];
    v.x = fmaxf(v.x * sc.x + sh.x, 0.f);
    v.y = fmaxf(v.y * sc.y + sh.y, 0.f);
    v.z = fmaxf(v.z * sc.z + sh.z, 0.f);
    v.w = fmaxf(v.w * sc.w + sh.w, 0.f);
    if (mode == 1) {
        v.x = 1.f / (1.f + expf(-v.x));
        v.y = 1.f / (1.f + expf(-v.y));
        v.z = 1.f / (1.f + expf(-v.z));
        v.w = 1.f / (1.f + expf(-v.w));
    }
    ((float4*)g_h)[i] = v;
    if (mode == 0) ((float4*)g_y)[i] = v;   // layer2 accumulator init
}

// ---------------- per-graph mean pooling ----------------
__device__ __forceinline__ int lb_search(const void* bp, int target, bool i64) {
    int l = 0, r = NN;
    while (l < r) {
        int m = (l + r) >> 1;
        if (read_idx(bp, m, i64) < (long long)target) l = m + 1; else r = m;
    }
    return l;
}

__global__ void pool_kernel(const void* __restrict__ batchv) {
    const int g = blockIdx.x, c = threadIdx.x;
    const bool i64 = (g_idx64 != 0);
    int lo = lb_search(batchv, g, i64);
    int hi = lb_search(batchv, g + 1, i64);
    float s = 0.f;
    for (int i = lo; i < hi; i++) s += g_h[(size_t)i * HH + c];
    int cnt = hi - lo;
    g_pooled[g * HH + c] = s / fmaxf((float)cnt, 1.f);
}

// ---------------- fused action MLP ----------------
__device__ __forceinline__ void mlp_layer(float* z, const float* p_s,
                                          const float* __restrict__ Wrow,
                                          float bias, float gamma, float beta) {
#pragma unroll
    for (int r = 0; r < GG; r++) z[r] = bias;
    for (int k = 0; k < HH; k += 4) {
        float4 w = *(const float4*)(Wrow + k);
#pragma unroll
        for (int r = 0; r < GG; r++) {
            float4 p = *(const float4*)(p_s + r * HH + k);
            z[r] += w.x * p.x + w.y * p.y + w.z * p.z + w.w * p.w;
        }
    }
    float m = 0.f, s2 = 0.f;
#pragma unroll
    for (int r = 0; r < GG; r++) { m += z[r]; s2 += z[r] * z[r]; }
    m *= (1.f / GG);
    float v = s2 * (1.f / GG) - m * m;
    float sc = rsqrtf(v + BN_EPS) * gamma;
    float sh = beta - m * sc;
#pragma unroll
    for (int r = 0; r < GG; r++) z[r] = fmaxf(z[r] * sc + sh, 0.f);
}

__global__ void __launch_bounds__(128) mlp_kernel(
    const float* __restrict__ A1w, const float* __restrict__ A1b,
    const float* __restrict__ Ag1, const float* __restrict__ Ab1,
    const float* __restrict__ A2w, const float* __restrict__ A2b,
    const float* __restrict__ Ag2, const float* __restrict__ Ab2,
    const float* __restrict__ A3w, const float* __restrict__ A3b,
    float* __restrict__ out)
{
    __shared__ float p_s[GG * HH];
    const int c = threadIdx.x;
    for (int idx = c; idx < GG * HH; idx += 128) p_s[idx] = g_pooled[idx];
    __syncthreads();

    float z[GG];
    mlp_layer(z, p_s, A1w + c * HH, A1b[c], Ag1[c], Ab1[c]);
    __syncthreads();
#pragma unroll
    for (int r = 0; r < GG; r++) p_s[r * HH + c] = z[r];
    __syncthreads();

    mlp_layer(z, p_s, A2w + c * HH, A2b[c], Ag2[c], Ab2[c]);
    __syncthreads();
#pragma unroll
    for (int r = 0; r < GG; r++) p_s[r * HH + c] = z[r];
    __syncthreads();

    for (int idx = c; idx < GG * AA; idx += 128) {
        int r = idx >> 4, a2 = idx & 15;
        float acc = A3b[a2];
        for (int k = 0; k < HH; k++) acc += p_s[r * HH + k] * A3w[a2 * HH + k];
        out[idx] = 1.f / (1.f + expf(-acc));
    }
}

// ---------------- host launch ----------------
extern "C" void kernel_launch(void* const* d_in, const int* in_sizes, int n_in,
                              void* d_out, int out_size) {
    int ix, iea, iei, ib;
    int iW1, ib1, iWe1, ibe1, ig1, ibt1, iW2, ib2, iWe2, ibe2, ig2, ibt2;
    int iA1w, iA1b, iAg1, iAb1, iA2w, iA2b, iAg2, iAb2, iA3w, iA3b;
    if (in_sizes[2] == 2 * EE || in_sizes[2] == 4 * EE) {
        ix = 0; iea = 1; iei = 2; ib = 3;
        iW1 = 4; ib1 = 5; iWe1 = 6; ibe1 = 7; ig1 = 8; ibt1 = 9;
        iW2 = 10; ib2 = 11; iWe2 = 12; ibe2 = 13; ig2 = 14; ibt2 = 15;
        iA1w = 16; iA1b = 17; iAg1 = 18; iAb1 = 19;
        iA2w = 20; iA2b = 21; iAg2 = 22; iAb2 = 23; iA3w = 24; iA3b = 25;
    } else {
        ix = 0; iea = 1;
        iW1 = 2; ib1 = 3; iWe1 = 4; ibe1 = 5; ig1 = 6; ibt1 = 7;
        iW2 = 8; ib2 = 9; iWe2 = 10; ibe2 = 11; ig2 = 12; ibt2 = 13;
        iA1w = 14; iA1b = 15; iAg1 = 16; iAb1 = 17;
        iA2w = 18; iA2b = 19; iAg2 = 20; iAb2 = 21; iA3w = 22; iA3b = 23;
        iei = 24; ib = 25;
    }

    const float* x   = (const float*)d_in[ix];
    const float* ea  = (const float*)d_in[iea];
    const void*  ei  = d_in[iei];
    const void*  bat = d_in[ib];
    float* out = (float*)d_out;

    const int n4 = NN * HH / 4;
    const int copy_blocks = (n4 + 255) / 256;
    const int edge_blocks = (NTILES + 63) / 64;      // 782
    const int gemm_blocks = (NN + 127) / 128;        // 391

    // launch indices: detect=0, copy=1, edge1=2, gemm1=3 (ncu-profiled slot)
    detect_kernel<<<1, 256>>>((const unsigned int*)ei);
    copy_init_kernel<<<copy_blocks, 256>>>((const float4*)x, n4);

    // ---- layer 1 ----
    edge_mma_kernel<<<edge_blocks, 256>>>(x, 0, ea, ei,
                                          (const float*)d_in[iWe1], (const float*)d_in[ibe1]);
    node_gemm_mma_kernel<<<gemm_blocks, 512>>>((const float*)d_in[iW1], (const float*)d_in[ib1]);
    normalize_kernel<<<copy_blocks, 256>>>(0, n4, (const float*)d_in[ig1], (const float*)d_in[ibt1]);

    // ---- layer 2 ----
    edge_mma_kernel<<<edge_blocks, 256>>>(x, 1, ea, ei,
                                          (const float*)d_in[iWe2], (const float*)d_in[ibe2]);
    node_gemm_mma_kernel<<<gemm_blocks, 512>>>((const float*)d_in[iW2], (const float*)d_in[ib2]);
    normalize_kernel<<<copy_blocks, 256>>>(1, n4, (const float*)d_in[ig2], (const float*)d_in[ibt2]);

    // ---- pool + MLP ----
    pool_kernel<<<GG, 128>>>(bat);
    mlp_kernel<<<1, 128>>>((const float*)d_in[iA1w], (const float*)d_in[iA1b],
                           (const float*)d_in[iAg1], (const float*)d_in[iAb1],
                           (const float*)d_in[iA2w], (const float*)d_in[iA2b],
                           (const float*)d_in[iAg2], (const float*)d_in[iAb2],
                           (const float*)d_in[iA3w], (const float*)d_in[iA3b], out);
}

// round 15
// speedup vs baseline: 1.0493x; 1.0174x over previous
#include <cuda_runtime.h>
#include <cuda_bf16.h>
#include <math.h>

#define NN 50000
#define EE 800000
#define HH 128
#define EDIM 32
#define GG 64
#define AA 16
#define BN_EPS 1e-5f
#define FULLM 0xffffffffu
#define TS 72   // smem tile row stride (floats): conflict-free STS.64/LDS.128

// ---------------- scratch (static device globals; no allocation) ----------------
__device__ float g_y[(size_t)NN * HH];
__device__ float g_u[(size_t)NN * HH];
__device__ float g_h[(size_t)NN * HH];
__device__ float g_sum[HH];
__device__ float g_sumsq[HH];
__device__ float g_pooled[GG * HH];
__device__ int   g_idx64;

// ---------------- int32/int64 index handling ----------------
__device__ __forceinline__ long long read_idx(const void* p, long long i, bool i64) {
    if (i64) return ((const long long*)p)[i];
    return (long long)((const int*)p)[i];
}

__global__ void detect_kernel(const unsigned int* __restrict__ w) {
    __shared__ int f;
    if (threadIdx.x == 0) f = 0;
    __syncthreads();
    int local = 0;
    for (int i = threadIdx.x * 2 + 1; i < 8192; i += 512)
        if (w[i]) local = 1;
    if (local) atomicOr(&f, 1);
    __syncthreads();
    if (threadIdx.x == 0) g_idx64 = f ? 0 : 1;
}

// ---------------- bf16 2-split helpers ----------------
__device__ __forceinline__ unsigned pack2(float e0, float e1) {
    unsigned r;
    asm("cvt.rn.bf16x2.f32 %0, %1, %2;" : "=r"(r) : "f"(e1), "f"(e0));
    return r;
}
__device__ __forceinline__ void split2(float e0, float e1, unsigned& hi, unsigned& lo) {
    hi = pack2(e0, e1);
    float f0 = __uint_as_float(hi << 16);
    float f1 = __uint_as_float(hi & 0xffff0000u);
    lo = pack2(e0 - f0, e1 - f1);
}
__device__ __forceinline__ void mma_bf16(float& c0, float& c1, float& c2, float& c3,
                                         unsigned a0, unsigned a1, unsigned a2, unsigned a3,
                                         unsigned b0, unsigned b1) {
    asm volatile("mma.sync.aligned.m16n8k16.row.col.f32.bf16.bf16.f32 "
                 "{%0,%1,%2,%3}, {%4,%5,%6,%7}, {%8,%9}, {%0,%1,%2,%3};"
                 : "+f"(c0), "+f"(c1), "+f"(c2), "+f"(c3)
                 : "r"(a0), "r"(a1), "r"(a2), "r"(a3), "r"(b0), "r"(b1));
}

// Stage pre-split B fragments for one k32 block (1024 float4).
__device__ __forceinline__ void stage_bfrag(float4* bfrag, const float* __restrict__ Wmat,
                                            int ldw, int kbase, int tid, int nthreads) {
    for (int idx = tid; idx < 1024; idx += nthreads) {
        int nt = idx >> 6, kc = (idx >> 5) & 1, ln = idx & 31;
        int g2 = ln >> 2, t2 = ln & 3;
        int c = nt * 8 + g2;
        int k0 = kbase + 16 * kc + 2 * t2;
        float w00 = Wmat[c * ldw + k0];
        float w01 = Wmat[c * ldw + k0 + 1];
        float w10 = Wmat[c * ldw + k0 + 8];
        float w11 = Wmat[c * ldw + k0 + 9];
        unsigned bh0, bl0, bh1, bl1;
        split2(w00, w01, bh0, bl0);
        split2(w10, w11, bh1, bl1);
        bfrag[idx] = make_float4(__uint_as_float(bh0), __uint_as_float(bh1),
                                 __uint_as_float(bl0), __uint_as_float(bl1));
    }
}

// Load raw A data (2 rows x one k32 block) as 8 float2.
__device__ __forceinline__ void load_a_raw(const float* __restrict__ row0,
                                           const float* __restrict__ row1,
                                           int kbase, int t, float2 A[8]) {
#pragma unroll
    for (int kc = 0; kc < 2; kc++) {
        int k0 = kbase + 16 * kc + 2 * t;
        A[kc * 4 + 0] = *(const float2*)(row0 + k0);
        A[kc * 4 + 1] = *(const float2*)(row1 + k0);
        A[kc * 4 + 2] = *(const float2*)(row0 + k0 + 8);
        A[kc * 4 + 3] = *(const float2*)(row1 + k0 + 8);
    }
}
__device__ __forceinline__ void split_a(const float2 A[8],
                                        unsigned ahi[2][4], unsigned alo[2][4]) {
#pragma unroll
    for (int kc = 0; kc < 2; kc++) {
        split2(A[kc * 4 + 0].x, A[kc * 4 + 0].y, ahi[kc][0], alo[kc][0]);
        split2(A[kc * 4 + 1].x, A[kc * 4 + 1].y, ahi[kc][1], alo[kc][1]);
        split2(A[kc * 4 + 2].x, A[kc * 4 + 2].y, ahi[kc][2], alo[kc][2]);
        split2(A[kc * 4 + 3].x, A[kc * 4 + 3].y, ahi[kc][3], alo[kc][3]);
    }
}

// ---------------- y = src (copy) + zero BN stats ----------------
__global__ void copy_init_kernel(const float4* __restrict__ src, int n4) {
    if (blockIdx.x == 0 && threadIdx.x < HH) {
        g_sum[threadIdx.x] = 0.f;
        g_sumsq[threadIdx.x] = 0.f;
    }
    int i = blockIdx.x * blockDim.x + threadIdx.x;
    if (i < n4) ((float4*)g_y)[i] = src[i];
}

// ---------------- edge kernel: mma elin + smem-tiled coalesced epilogue ----------------
#define NTILES 50000         // EE/16
#define WTILES 8
__global__ void __launch_bounds__(256, 2) edge_mma_kernel(
    const float* __restrict__ xin_ext, int use_h,
    const float* __restrict__ ea,
    const void* __restrict__ eiv,
    const float* __restrict__ We,   // [128][32] row-major
    const float* __restrict__ be)
{
    __shared__ float4 bfrag[1024];        // 16KB
    __shared__ float be_s[HH];
    __shared__ float sbuf[8][16 * TS];    // per-warp [16 edges][64 cols padded]  36.9KB

    const int tid = threadIdx.x;
    // layer 2: re-zero BN stats for the upcoming gemm (edge2 strictly precedes gemm2,
    // and normalize1 — the last reader of the old stats — precedes edge2)
    if (use_h && blockIdx.x == 0 && tid < HH) {
        g_sum[tid] = 0.f;
        g_sumsq[tid] = 0.f;
    }
    stage_bfrag(bfrag, We, EDIM, 0, tid, 256);
    if (tid < HH) be_s[tid] = be[tid];
    __syncthreads();

    const float* __restrict__ xin = use_h ? g_h : xin_ext;
    const int lane = tid & 31, warp = tid >> 5;
    const int g = lane >> 2, t = lane & 3;
    const bool i64 = (g_idx64 != 0);
    const int half16 = lane >> 4;        // 0/1: which of 2 edges per epilogue iter
    const int li = lane & 15;            // column quad within edge half-row
    float* buf = sbuf[warp];
    const int base = (blockIdx.x * 8 + warp) * WTILES;

    int nt_here = NTILES - base;
    if (nt_here <= 0) return;
    if (nt_here > WTILES) nt_here = WTILES;

    for (int it = 0; it < nt_here; it++) {
        long long e0 = (long long)(base + it) * 16;
        int svC = 0, dvC = 0;
        if (lane < 16) {
            svC = (int)read_idx(eiv, e0 + lane, i64);
            dvC = (int)read_idx(eiv, (long long)EE + e0 + lane, i64);
        }
        float2 Ac[8];
        load_a_raw(ea + (size_t)(e0 + g) * EDIM, ea + (size_t)(e0 + g + 8) * EDIM, 0, t, Ac);

        unsigned ahi[2][4], alo[2][4];
        split_a(Ac, ahi, alo);

#pragma unroll
        for (int h = 0; h < 2; h++) {
            // ---- phase A: mma for cols [h*64, h*64+64), write to smem tile ----
#pragma unroll
            for (int ntl = 0; ntl < 8; ntl++) {
                int nt = h * 8 + ntl;
                float2 b2 = *(const float2*)(be_s + nt * 8 + 2 * t);
                float c0 = b2.x, c1 = b2.y, c2 = b2.x, c3 = b2.y;
#pragma unroll
                for (int kc = 0; kc < 2; kc++) {
                    float4 bf = bfrag[(nt * 2 + kc) * 32 + lane];
                    unsigned bh0 = __float_as_uint(bf.x), bh1 = __float_as_uint(bf.y);
                    unsigned bl0 = __float_as_uint(bf.z), bl1 = __float_as_uint(bf.w);
                    mma_bf16(c0, c1, c2, c3, ahi[kc][0], ahi[kc][1], ahi[kc][2], ahi[kc][3], bh0, bh1);
                    mma_bf16(c0, c1, c2, c3, alo[kc][0], alo[kc][1], alo[kc][2], alo[kc][3], bh0, bh1);
                    mma_bf16(c0, c1, c2, c3, ahi[kc][0], ahi[kc][1], ahi[kc][2], ahi[kc][3], bl0, bl1);
                }
                int cw = ntl * 8 + 2 * t;
                *(float2*)(buf + g * TS + cw)       = make_float2(c0, c1);
                *(float2*)(buf + (g + 8) * TS + cw) = make_float2(c2, c3);
            }
            __syncwarp();

            // ---- phase B: coalesced gather + relu + red, 2 edges x 64 cols per iter ----
#pragma unroll
            for (int g2 = 0; g2 < 4; g2++) {
                float4 m0, m1, xv0, xv1;
                int e0i = 4 * g2 + half16;       // edges e0i and e0i+2
                int e1i = e0i + 2;
                int s0 = __shfl_sync(FULLM, svC, e0i);
                int s1 = __shfl_sync(FULLM, svC, e1i);
                m0 = *(const float4*)(buf + e0i * TS + 4 * li);
                m1 = *(const float4*)(buf + e1i * TS + 4 * li);
                xv0 = *(const float4*)(xin + (size_t)s0 * HH + h * 64 + 4 * li);
                xv1 = *(const float4*)(xin + (size_t)s1 * HH + h * 64 + 4 * li);
                int d0 = __shfl_sync(FULLM, dvC, e0i);
                int d1 = __shfl_sync(FULLM, dvC, e1i);
                {
                    float o0 = fmaxf(m0.x + xv0.x, 0.f);
                    float o1 = fmaxf(m0.y + xv0.y, 0.f);
                    float o2 = fmaxf(m0.z + xv0.z, 0.f);
                    float o3 = fmaxf(m0.w + xv0.w, 0.f);
                    asm volatile("red.global.add.v4.f32 [%0], {%1,%2,%3,%4};"
                                 :: "l"(g_y + (size_t)d0 * HH + h * 64 + 4 * li),
                                    "f"(o0), "f"(o1), "f"(o2), "f"(o3) : "memory");
                }
                {
                    float o0 = fmaxf(m1.x + xv1.x, 0.f);
                    float o1 = fmaxf(m1.y + xv1.y, 0.f);
                    float o2 = fmaxf(m1.z + xv1.z, 0.f);
                    float o3 = fmaxf(m1.w + xv1.w, 0.f);
                    asm volatile("red.global.add.v4.f32 [%0], {%1,%2,%3,%4};"
                                 :: "l"(g_y + (size_t)d1 * HH + h * 64 + 4 * li),
                                    "f"(o0), "f"(o1), "f"(o2), "f"(o3) : "memory");
                }
            }
            __syncwarp();
        }
    }
}

// ---------------- node GEMM + fused BN sums, double-buffered, 2 blocks/SM ----------------
// 512 threads, 16 warps. Warp: 16 rows x 64 cols. Block: 128 rows x 128 cols.
__global__ void __launch_bounds__(512, 2) node_gemm_mma_kernel(
    const float* __restrict__ W,
    const float* __restrict__ b)
{
    __shared__ float4 bfrag[2][1024];   // double-buffered, 32KB
    __shared__ float b_s[HH];
    __shared__ float s_sum[HH], s_sumsq[HH];

    const int tid = threadIdx.x;
    const int lane = tid & 31, warp = tid >> 5;
    const int g = lane >> 2, t = lane & 3;
    const int colhalf = warp >> 3;
    const int rw = warp & 7;
    const int nt0 = colhalf * 8;
    const int rowbase = blockIdx.x * 128 + rw * 16;
    const bool active = (rowbase < NN);      // NN % 16 == 0
    const bool even = ((t & 1) == 0);
    const int cboff = (t & 2) ? 4 : 0;

    if (tid < HH) {
        b_s[tid] = b[tid];
        s_sum[tid] = 0.f;
        s_sumsq[tid] = 0.f;
    }

    float C[8][4];
#pragma unroll
    for (int nt = 0; nt < 8; nt++)
#pragma unroll
        for (int q = 0; q < 4; q++) C[nt][q] = 0.f;

    const float* row0 = g_y + (size_t)(rowbase + g) * HH;
    const float* row1 = g_y + (size_t)(rowbase + g + 8) * HH;

    stage_bfrag(bfrag[0], W, HH, 0, tid, 512);
    __syncthreads();

#pragma unroll
    for (int kb = 0; kb < 4; kb++) {
        // stage next k-block into the other buffer (overlaps with mma below)
        if (kb + 1 < 4)
            stage_bfrag(bfrag[(kb + 1) & 1], W, HH, (kb + 1) * 32, tid, 512);

        if (active) {
            const float4* bcur = bfrag[kb & 1];
            float2 A[8];
            load_a_raw(row0, row1, kb * 32, t, A);
            unsigned ahi[2][4], alo[2][4];
            split_a(A, ahi, alo);

#pragma unroll
            for (int ntl = 0; ntl < 8; ntl++) {
                int nt = nt0 + ntl;
#pragma unroll
                for (int kc = 0; kc < 2; kc++) {
                    float4 bf = bcur[(nt * 2 + kc) * 32 + lane];
                    unsigned bh0 = __float_as_uint(bf.x), bh1 = __float_as_uint(bf.y);
                    unsigned bl0 = __float_as_uint(bf.z), bl1 = __float_as_uint(bf.w);
                    mma_bf16(C[ntl][0], C[ntl][1], C[ntl][2], C[ntl][3],
                             ahi[kc][0], ahi[kc][1], ahi[kc][2], ahi[kc][3], bh0, bh1);
                    mma_bf16(C[ntl][0], C[ntl][1], C[ntl][2], C[ntl][3],
                             alo[kc][0], alo[kc][1], alo[kc][2], alo[kc][3], bh0, bh1);
                    mma_bf16(C[ntl][0], C[ntl][1], C[ntl][2], C[ntl][3],
                             ahi[kc][0], ahi[kc][1], ahi[kc][2], ahi[kc][3], bl0, bl1);
                }
            }
        }
        __syncthreads();   // staging of kb+1 done; all reads of bfrag[kb&1] done
    }

    if (active) {
        const int orow = rowbase + (even ? g : g + 8);
        float* outp = g_u + (size_t)orow * HH + cboff;
#pragma unroll
        for (int ntl = 0; ntl < 8; ntl++) {
            int nt = nt0 + ntl;
            float c0 = C[ntl][0] + b_s[nt * 8 + 2 * t];
            float c1 = C[ntl][1] + b_s[nt * 8 + 2 * t + 1];
            float c2 = C[ntl][2] + b_s[nt * 8 + 2 * t];
            float c3 = C[ntl][3] + b_s[nt * 8 + 2 * t + 1];

            // ---- BN column sums over this warp's 16 rows -> smem staging ----
            float s0 = c0 + c2, s1 = c1 + c3;
            float q0 = c0 * c0 + c2 * c2, q1 = c1 * c1 + c3 * c3;
#pragma unroll
            for (int m = 4; m <= 16; m <<= 1) {
                s0 += __shfl_xor_sync(FULLM, s0, m);
                s1 += __shfl_xor_sync(FULLM, s1, m);
                q0 += __shfl_xor_sync(FULLM, q0, m);
                q1 += __shfl_xor_sync(FULLM, q1, m);
            }
            if (g == 0) {   // lanes 0-3: one contribution per column pair
                int col = nt * 8 + 2 * t;
                atomicAdd(&s_sum[col], s0);
                atomicAdd(&s_sum[col + 1], s1);
                atomicAdd(&s_sumsq[col], q0);
                atomicAdd(&s_sumsq[col + 1], q1);
            }

            float e0 = even ? c2 : c0;
            float e1 = even ? c3 : c1;
            float r0 = __shfl_xor_sync(FULLM, e0, 1);
            float r1 = __shfl_xor_sync(FULLM, e1, 1);
            float4 o;
            if (even) { o = make_float4(c0, c1, r0, r1); }
            else      { o = make_float4(r0, r1, c2, c3); }
            *(float4*)(outp + nt * 8) = o;
        }
    }

    // ---- flush block sums: 128 global atomics per block ----
    __syncthreads();
    if (tid < HH) {
        atomicAdd(&g_sum[tid], s_sum[tid]);
        atomicAdd(&g_sumsq[tid], s_sumsq[tid]);
    }
}

// ---------------- normalize (stats computed in-block): h = act(u*scale+shift) ----------------
__global__ void normalize_kernel(int mode, int n4,
                                 const float* __restrict__ gamma,
                                 const float* __restrict__ beta) {
    __shared__ float sc_s[HH], sh_s[HH];
    if (threadIdx.x < HH) {
        int c = threadIdx.x;
        float m = g_sum[c] * (1.f / NN);
        float v = g_sumsq[c] * (1.f / NN) - m * m;
        float rs = rsqrtf(v + BN_EPS);
        float sc = rs * gamma[c];
        sc_s[c] = sc;
        sh_s[c] = beta[c] - m * sc;
    }
    __syncthreads();

    int i = blockIdx.x * blockDim.x + threadIdx.x;
    if (i >= n4) return;
    int c0 = (i * 4) & 127;
    float4 sc = *(const float4*)(sc_s + c0);
    float4 sh = *(const float4*)(sh_s + c0);
    float4 v = ((const float4*)g_u)[i];
    v.x = fmaxf(v.x * sc.x + sh.x, 0.f);
    v.y = fmaxf(v.y * sc.y + sh.y, 0.f);
    v.z = fmaxf(v.z * sc.z + sh.z, 0.f);
    v.w = fmaxf(v.w * sc.w + sh.w, 0.f);
    if (mode == 1) {
        v.x = 1.f / (1.f + expf(-v.x));
        v.y = 1.f / (1.f + expf(-v.y));
        v.z = 1.f / (1.f + expf(-v.z));
        v.w = 1.f / (1.f + expf(-v.w));
    }
    ((float4*)g_h)[i] = v;
    if (mode == 0) ((float4*)g_y)[i] = v;   // layer2 accumulator init
}

// ---------------- per-graph mean pooling ----------------
__device__ __forceinline__ int lb_search(const void* bp, int target, bool i64) {
    int l = 0, r = NN;
    while (l < r) {
        int m = (l + r) >> 1;
        if (read_idx(bp, m, i64) < (long long)target) l = m + 1; else r = m;
    }
    return l;
}

__global__ void pool_kernel(const void* __restrict__ batchv) {
    const int g = blockIdx.x, c = threadIdx.x;
    const bool i64 = (g_idx64 != 0);
    int lo = lb_search(batchv, g, i64);
    int hi = lb_search(batchv, g + 1, i64);
    float s = 0.f;
    for (int i = lo; i < hi; i++) s += g_h[(size_t)i * HH + c];
    int cnt = hi - lo;
    g_pooled[g * HH + c] = s / fmaxf((float)cnt, 1.f);
}

// ---------------- fused action MLP ----------------
__device__ __forceinline__ void mlp_layer(float* z, const float* p_s,
                                          const float* __restrict__ Wrow,
                                          float bias, float gamma, float beta) {
#pragma unroll
    for (int r = 0; r < GG; r++) z[r] = bias;
    for (int k = 0; k < HH; k += 4) {
        float4 w = *(const float4*)(Wrow + k);
#pragma unroll
        for (int r = 0; r < GG; r++) {
            float4 p = *(const float4*)(p_s + r * HH + k);
            z[r] += w.x * p.x + w.y * p.y + w.z * p.z + w.w * p.w;
        }
    }
    float m = 0.f, s2 = 0.f;
#pragma unroll
    for (int r = 0; r < GG; r++) { m += z[r]; s2 += z[r] * z[r]; }
    m *= (1.f / GG);
    float v = s2 * (1.f / GG) - m * m;
    float sc = rsqrtf(v + BN_EPS) * gamma;
    float sh = beta - m * sc;
#pragma unroll
    for (int r = 0; r < GG; r++) z[r] = fmaxf(z[r] * sc + sh, 0.f);
}

__global__ void __launch_bounds__(128) mlp_kernel(
    const float* __restrict__ A1w, const float* __restrict__ A1b,
    const float* __restrict__ Ag1, const float* __restrict__ Ab1,
    const float* __restrict__ A2w, const float* __restrict__ A2b,
    const float* __restrict__ Ag2, const float* __restrict__ Ab2,
    const float* __restrict__ A3w, const float* __restrict__ A3b,
    float* __restrict__ out)
{
    __shared__ float p_s[GG * HH];
    const int c = threadIdx.x;
    for (int idx = c; idx < GG * HH; idx += 128) p_s[idx] = g_pooled[idx];
    __syncthreads();

    float z[GG];
    mlp_layer(z, p_s, A1w + c * HH, A1b[c], Ag1[c], Ab1[c]);
    __syncthreads();
#pragma unroll
    for (int r = 0; r < GG; r++) p_s[r * HH + c] = z[r];
    __syncthreads();

    mlp_layer(z, p_s, A2w + c * HH, A2b[c], Ag2[c], Ab2[c]);
    __syncthreads();
#pragma unroll
    for (int r = 0; r < GG; r++) p_s[r * HH + c] = z[r];
    __syncthreads();

    for (int idx = c; idx < GG * AA; idx += 128) {
        int r = idx >> 4, a2 = idx & 15;
        float acc = A3b[a2];
        for (int k = 0; k < HH; k++) acc += p_s[r * HH + k] * A3w[a2 * HH + k];
        out[idx] = 1.f / (1.f + expf(-acc));
    }
}

// ---------------- host launch ----------------
extern "C" void kernel_launch(void* const* d_in, const int* in_sizes, int n_in,
                              void* d_out, int out_size) {
    int ix, iea, iei, ib;
    int iW1, ib1, iWe1, ibe1, ig1, ibt1, iW2, ib2, iWe2, ibe2, ig2, ibt2;
    int iA1w, iA1b, iAg1, iAb1, iA2w, iA2b, iAg2, iAb2, iA3w, iA3b;
    if (in_sizes[2] == 2 * EE || in_sizes[2] == 4 * EE) {
        ix = 0; iea = 1; iei = 2; ib = 3;
        iW1 = 4; ib1 = 5; iWe1 = 6; ibe1 = 7; ig1 = 8; ibt1 = 9;
        iW2 = 10; ib2 = 11; iWe2 = 12; ibe2 = 13; ig2 = 14; ibt2 = 15;
        iA1w = 16; iA1b = 17; iAg1 = 18; iAb1 = 19;
        iA2w = 20; iA2b = 21; iAg2 = 22; iAb2 = 23; iA3w = 24; iA3b = 25;
    } else {
        ix = 0; iea = 1;
        iW1 = 2; ib1 = 3; iWe1 = 4; ibe1 = 5; ig1 = 6; ibt1 = 7;
        iW2 = 8; ib2 = 9; iWe2 = 10; ibe2 = 11; ig2 = 12; ibt2 = 13;
        iA1w = 14; iA1b = 15; iAg1 = 16; iAb1 = 17;
        iA2w = 18; iA2b = 19; iAg2 = 20; iAb2 = 21; iA3w = 22; iA3b = 23;
        iei = 24; ib = 25;
    }

    const float* x   = (const float*)d_in[ix];
    const float* ea  = (const float*)d_in[iea];
    const void*  ei  = d_in[iei];
    const void*  bat = d_in[ib];
    float* out = (float*)d_out;

    const int n4 = NN * HH / 4;
    const int copy_blocks = (n4 + 255) / 256;
    const int edge_blocks = (NTILES + 63) / 64;      // 782
    const int gemm_blocks = (NN + 127) / 128;        // 391

    // launch indices: detect=0, copy=1, edge1=2, gemm1=3 (ncu-profiled slot)
    detect_kernel<<<1, 256>>>((const unsigned int*)ei);
    copy_init_kernel<<<copy_blocks, 256>>>((const float4*)x, n4);

    // ---- layer 1 ----
    edge_mma_kernel<<<edge_blocks, 256>>>(x, 0, ea, ei,
                                          (const float*)d_in[iWe1], (const float*)d_in[ibe1]);
    node_gemm_mma_kernel<<<gemm_blocks, 512>>>((const float*)d_in[iW1], (const float*)d_in[ib1]);
    normalize_kernel<<<copy_blocks, 256>>>(0, n4, (const float*)d_in[ig1], (const float*)d_in[ibt1]);

    // ---- layer 2 ----
    edge_mma_kernel<<<edge_blocks, 256>>>(x, 1, ea, ei,
                                          (const float*)d_in[iWe2], (const float*)d_in[ibe2]);
    node_gemm_mma_kernel<<<gemm_blocks, 512>>>((const float*)d_in[iW2], (const float*)d_in[ib2]);
    normalize_kernel<<<copy_blocks, 256>>>(1, n4, (const float*)d_in[ig2], (const float*)d_in[ibt2]);

    // ---- pool + MLP ----
    pool_kernel<<<GG, 128>>>(bat);
    mlp_kernel<<<1, 128>>>((const float*)d_in[iA1w], (const float*)d_in[iA1b],
                           (const float*)d_in[iAg1], (const float*)d_in[iAb1],
                           (const float*)d_in[iA2w], (const float*)d_in[iA2b],
                           (const float*)d_in[iAg2], (const float*)d_in[iAb2],
                           (const float*)d_in[iA3w], (const float*)d_in[iA3b], out);
}

// round 16
// speedup vs baseline: 1.0704x; 1.0201x over previous
#include <cuda_runtime.h>
#include <cuda_bf16.h>
#include <math.h>

#define NN 50000
#define EE 800000
#define HH 128
#define EDIM 32
#define GG 64
#define AA 16
#define BN_EPS 1e-5f
#define FULLM 0xffffffffu
#define TS 72   // smem tile row stride (floats): conflict-free STS.64/LDS.128

// ---------------- scratch (static device globals; no allocation) ----------------
__device__ float g_y[(size_t)NN * HH];
__device__ float g_u[(size_t)NN * HH];
__device__ float g_h[(size_t)NN * HH];
__device__ float g_sum[HH];
__device__ float g_sumsq[HH];
__device__ float g_pooled[GG * HH];
__device__ int   g_idx64;

// ---------------- int32/int64 index handling ----------------
__device__ __forceinline__ long long read_idx(const void* p, long long i, bool i64) {
    if (i64) return ((const long long*)p)[i];
    return (long long)((const int*)p)[i];
}

__global__ void detect_kernel(const unsigned int* __restrict__ w) {
    __shared__ int f;
    if (threadIdx.x == 0) f = 0;
    __syncthreads();
    int local = 0;
    for (int i = threadIdx.x * 2 + 1; i < 8192; i += 512)
        if (w[i]) local = 1;
    if (local) atomicOr(&f, 1);
    __syncthreads();
    if (threadIdx.x == 0) g_idx64 = f ? 0 : 1;
}

// ---------------- bf16 2-split helpers ----------------
__device__ __forceinline__ unsigned pack2(float e0, float e1) {
    unsigned r;
    asm("cvt.rn.bf16x2.f32 %0, %1, %2;" : "=r"(r) : "f"(e1), "f"(e0));
    return r;
}
__device__ __forceinline__ void split2(float e0, float e1, unsigned& hi, unsigned& lo) {
    hi = pack2(e0, e1);
    float f0 = __uint_as_float(hi << 16);
    float f1 = __uint_as_float(hi & 0xffff0000u);
    lo = pack2(e0 - f0, e1 - f1);
}
__device__ __forceinline__ void mma_bf16(float& c0, float& c1, float& c2, float& c3,
                                         unsigned a0, unsigned a1, unsigned a2, unsigned a3,
                                         unsigned b0, unsigned b1) {
    asm volatile("mma.sync.aligned.m16n8k16.row.col.f32.bf16.bf16.f32 "
                 "{%0,%1,%2,%3}, {%4,%5,%6,%7}, {%8,%9}, {%0,%1,%2,%3};"
                 : "+f"(c0), "+f"(c1), "+f"(c2), "+f"(c3)
                 : "r"(a0), "r"(a1), "r"(a2), "r"(a3), "r"(b0), "r"(b1));
}

// Stage pre-split B fragments for one k32 block (1024 float4).
__device__ __forceinline__ void stage_bfrag(float4* bfrag, const float* __restrict__ Wmat,
                                            int ldw, int kbase, int tid, int nthreads) {
    for (int idx = tid; idx < 1024; idx += nthreads) {
        int nt = idx >> 6, kc = (idx >> 5) & 1, ln = idx & 31;
        int g2 = ln >> 2, t2 = ln & 3;
        int c = nt * 8 + g2;
        int k0 = kbase + 16 * kc + 2 * t2;
        float w00 = Wmat[c * ldw + k0];
        float w01 = Wmat[c * ldw + k0 + 1];
        float w10 = Wmat[c * ldw + k0 + 8];
        float w11 = Wmat[c * ldw + k0 + 9];
        unsigned bh0, bl0, bh1, bl1;
        split2(w00, w01, bh0, bl0);
        split2(w10, w11, bh1, bl1);
        bfrag[idx] = make_float4(__uint_as_float(bh0), __uint_as_float(bh1),
                                 __uint_as_float(bl0), __uint_as_float(bl1));
    }
}

// Load raw A data (2 rows x one k32 block) as 8 float2.
__device__ __forceinline__ void load_a_raw(const float* __restrict__ row0,
                                           const float* __restrict__ row1,
                                           int kbase, int t, float2 A[8]) {
#pragma unroll
    for (int kc = 0; kc < 2; kc++) {
        int k0 = kbase + 16 * kc + 2 * t;
        A[kc * 4 + 0] = *(const float2*)(row0 + k0);
        A[kc * 4 + 1] = *(const float2*)(row1 + k0);
        A[kc * 4 + 2] = *(const float2*)(row0 + k0 + 8);
        A[kc * 4 + 3] = *(const float2*)(row1 + k0 + 8);
    }
}
__device__ __forceinline__ void split_a(const float2 A[8],
                                        unsigned ahi[2][4], unsigned alo[2][4]) {
#pragma unroll
    for (int kc = 0; kc < 2; kc++) {
        split2(A[kc * 4 + 0].x, A[kc * 4 + 0].y, ahi[kc][0], alo[kc][0]);
        split2(A[kc * 4 + 1].x, A[kc * 4 + 1].y, ahi[kc][1], alo[kc][1]);
        split2(A[kc * 4 + 2].x, A[kc * 4 + 2].y, ahi[kc][2], alo[kc][2]);
        split2(A[kc * 4 + 3].x, A[kc * 4 + 3].y, ahi[kc][3], alo[kc][3]);
    }
}

// ---------------- y = src (copy) + zero BN stats ----------------
__global__ void copy_init_kernel(const float4* __restrict__ src, int n4) {
    if (blockIdx.x == 0 && threadIdx.x < HH) {
        g_sum[threadIdx.x] = 0.f;
        g_sumsq[threadIdx.x] = 0.f;
    }
    int i = blockIdx.x * blockDim.x + threadIdx.x;
    if (i < n4) ((float4*)g_y)[i] = src[i];
}

// ---------------- edge kernel: mma elin + smem-tiled coalesced epilogue ----------------
#define NTILES 50000         // EE/16
#define WTILES 8
__global__ void __launch_bounds__(256, 2) edge_mma_kernel(
    const float* __restrict__ xin_ext, int use_h,
    const float* __restrict__ ea,
    const void* __restrict__ eiv,
    const float* __restrict__ We,   // [128][32] row-major
    const float* __restrict__ be)
{
    __shared__ float4 bfrag[1024];        // 16KB
    __shared__ float be_s[HH];
    __shared__ float sbuf[8][16 * TS];    // per-warp [16 edges][64 cols padded]  36.9KB

    const int tid = threadIdx.x;
    // layer 2: re-zero BN stats for the upcoming gemm (edge2 strictly precedes gemm2,
    // and normalize1 — the last reader of the old stats — precedes edge2)
    if (use_h && blockIdx.x == 0 && tid < HH) {
        g_sum[tid] = 0.f;
        g_sumsq[tid] = 0.f;
    }
    stage_bfrag(bfrag, We, EDIM, 0, tid, 256);
    if (tid < HH) be_s[tid] = be[tid];
    __syncthreads();

    const float* __restrict__ xin = use_h ? g_h : xin_ext;
    const int lane = tid & 31, warp = tid >> 5;
    const int g = lane >> 2, t = lane & 3;
    const bool i64 = (g_idx64 != 0);
    const int half16 = lane >> 4;        // 0/1: which of 2 edges per epilogue iter
    const int li = lane & 15;            // column quad within edge half-row
    float* buf = sbuf[warp];
    const int base = (blockIdx.x * 8 + warp) * WTILES;

    int nt_here = NTILES - base;
    if (nt_here <= 0) return;
    if (nt_here > WTILES) nt_here = WTILES;

    for (int it = 0; it < nt_here; it++) {
        long long e0 = (long long)(base + it) * 16;
        int svC = 0, dvC = 0;
        if (lane < 16) {
            svC = (int)read_idx(eiv, e0 + lane, i64);
            dvC = (int)read_idx(eiv, (long long)EE + e0 + lane, i64);
        }
        float2 Ac[8];
        load_a_raw(ea + (size_t)(e0 + g) * EDIM, ea + (size_t)(e0 + g + 8) * EDIM, 0, t, Ac);

        unsigned ahi[2][4], alo[2][4];
        split_a(Ac, ahi, alo);

#pragma unroll
        for (int h = 0; h < 2; h++) {
            // ---- phase A: mma for cols [h*64, h*64+64), write to smem tile ----
#pragma unroll
            for (int ntl = 0; ntl < 8; ntl++) {
                int nt = h * 8 + ntl;
                float2 b2 = *(const float2*)(be_s + nt * 8 + 2 * t);
                float c0 = b2.x, c1 = b2.y, c2 = b2.x, c3 = b2.y;
#pragma unroll
                for (int kc = 0; kc < 2; kc++) {
                    float4 bf = bfrag[(nt * 2 + kc) * 32 + lane];
                    unsigned bh0 = __float_as_uint(bf.x), bh1 = __float_as_uint(bf.y);
                    unsigned bl0 = __float_as_uint(bf.z), bl1 = __float_as_uint(bf.w);
                    mma_bf16(c0, c1, c2, c3, ahi[kc][0], ahi[kc][1], ahi[kc][2], ahi[kc][3], bh0, bh1);
                    mma_bf16(c0, c1, c2, c3, alo[kc][0], alo[kc][1], alo[kc][2], alo[kc][3], bh0, bh1);
                    mma_bf16(c0, c1, c2, c3, ahi[kc][0], ahi[kc][1], ahi[kc][2], ahi[kc][3], bl0, bl1);
                }
                int cw = ntl * 8 + 2 * t;
                *(float2*)(buf + g * TS + cw)       = make_float2(c0, c1);
                *(float2*)(buf + (g + 8) * TS + cw) = make_float2(c2, c3);
            }
            __syncwarp();

            // ---- phase B: coalesced gather + relu + red, 2 edges x 64 cols per iter ----
#pragma unroll
            for (int g2 = 0; g2 < 4; g2++) {
                float4 m0, m1, xv0, xv1;
                int e0i = 4 * g2 + half16;       // edges e0i and e0i+2
                int e1i = e0i + 2;
                int s0 = __shfl_sync(FULLM, svC, e0i);
                int s1 = __shfl_sync(FULLM, svC, e1i);
                m0 = *(const float4*)(buf + e0i * TS + 4 * li);
                m1 = *(const float4*)(buf + e1i * TS + 4 * li);
                xv0 = *(const float4*)(xin + (size_t)s0 * HH + h * 64 + 4 * li);
                xv1 = *(const float4*)(xin + (size_t)s1 * HH + h * 64 + 4 * li);
                int d0 = __shfl_sync(FULLM, dvC, e0i);
                int d1 = __shfl_sync(FULLM, dvC, e1i);
                {
                    float o0 = fmaxf(m0.x + xv0.x, 0.f);
                    float o1 = fmaxf(m0.y + xv0.y, 0.f);
                    float o2 = fmaxf(m0.z + xv0.z, 0.f);
                    float o3 = fmaxf(m0.w + xv0.w, 0.f);
                    asm volatile("red.global.add.v4.f32 [%0], {%1,%2,%3,%4};"
                                 :: "l"(g_y + (size_t)d0 * HH + h * 64 + 4 * li),
                                    "f"(o0), "f"(o1), "f"(o2), "f"(o3) : "memory");
                }
                {
                    float o0 = fmaxf(m1.x + xv1.x, 0.f);
                    float o1 = fmaxf(m1.y + xv1.y, 0.f);
                    float o2 = fmaxf(m1.z + xv1.z, 0.f);
                    float o3 = fmaxf(m1.w + xv1.w, 0.f);
                    asm volatile("red.global.add.v4.f32 [%0], {%1,%2,%3,%4};"
                                 :: "l"(g_y + (size_t)d1 * HH + h * 64 + 4 * li),
                                    "f"(o0), "f"(o1), "f"(o2), "f"(o3) : "memory");
                }
            }
            __syncwarp();
        }
    }
}

// ---------------- node GEMM + fused BN sums, double-buffered, 2 blocks/SM ----------------
// 512 threads, 16 warps. Warp: 16 rows x 64 cols. Block: 128 rows x 128 cols.
__global__ void __launch_bounds__(512, 2) node_gemm_mma_kernel(
    const float* __restrict__ W,
    const float* __restrict__ b)
{
    __shared__ float4 bfrag[2][1024];   // double-buffered, 32KB
    __shared__ float b_s[HH];
    __shared__ float s_sum[HH], s_sumsq[HH];

    const int tid = threadIdx.x;
    const int lane = tid & 31, warp = tid >> 5;
    const int g = lane >> 2, t = lane & 3;
    const int colhalf = warp >> 3;
    const int rw = warp & 7;
    const int nt0 = colhalf * 8;
    const int rowbase = blockIdx.x * 128 + rw * 16;
    const bool active = (rowbase < NN);      // NN % 16 == 0
    const bool even = ((t & 1) == 0);
    const int cboff = (t & 2) ? 4 : 0;

    if (tid < HH) {
        b_s[tid] = b[tid];
        s_sum[tid] = 0.f;
        s_sumsq[tid] = 0.f;
    }

    float C[8][4];
#pragma unroll
    for (int nt = 0; nt < 8; nt++)
#pragma unroll
        for (int q = 0; q < 4; q++) C[nt][q] = 0.f;

    const float* row0 = g_y + (size_t)(rowbase + g) * HH;
    const float* row1 = g_y + (size_t)(rowbase + g + 8) * HH;

    stage_bfrag(bfrag[0], W, HH, 0, tid, 512);
    __syncthreads();

#pragma unroll
    for (int kb = 0; kb < 4; kb++) {
        // stage next k-block into the other buffer (overlaps with mma below)
        if (kb + 1 < 4)
            stage_bfrag(bfrag[(kb + 1) & 1], W, HH, (kb + 1) * 32, tid, 512);

        if (active) {
            const float4* bcur = bfrag[kb & 1];
            float2 A[8];
            load_a_raw(row0, row1, kb * 32, t, A);
            unsigned ahi[2][4], alo[2][4];
            split_a(A, ahi, alo);

#pragma unroll
            for (int ntl = 0; ntl < 8; ntl++) {
                int nt = nt0 + ntl;
#pragma unroll
                for (int kc = 0; kc < 2; kc++) {
                    float4 bf = bcur[(nt * 2 + kc) * 32 + lane];
                    unsigned bh0 = __float_as_uint(bf.x), bh1 = __float_as_uint(bf.y);
                    unsigned bl0 = __float_as_uint(bf.z), bl1 = __float_as_uint(bf.w);
                    mma_bf16(C[ntl][0], C[ntl][1], C[ntl][2], C[ntl][3],
                             ahi[kc][0], ahi[kc][1], ahi[kc][2], ahi[kc][3], bh0, bh1);
                    mma_bf16(C[ntl][0], C[ntl][1], C[ntl][2], C[ntl][3],
                             alo[kc][0], alo[kc][1], alo[kc][2], alo[kc][3], bh0, bh1);
                    mma_bf16(C[ntl][0], C[ntl][1], C[ntl][2], C[ntl][3],
                             ahi[kc][0], ahi[kc][1], ahi[kc][2], ahi[kc][3], bl0, bl1);
                }
            }
        }
        __syncthreads();   // staging of kb+1 done; all reads of bfrag[kb&1] done
    }

    if (active) {
        const int orow = rowbase + (even ? g : g + 8);
        float* outp = g_u + (size_t)orow * HH + cboff;
#pragma unroll
        for (int ntl = 0; ntl < 8; ntl++) {
            int nt = nt0 + ntl;
            float c0 = C[ntl][0] + b_s[nt * 8 + 2 * t];
            float c1 = C[ntl][1] + b_s[nt * 8 + 2 * t + 1];
            float c2 = C[ntl][2] + b_s[nt * 8 + 2 * t];
            float c3 = C[ntl][3] + b_s[nt * 8 + 2 * t + 1];

            // ---- BN column sums over this warp's 16 rows -> smem staging ----
            float s0 = c0 + c2, s1 = c1 + c3;
            float q0 = c0 * c0 + c2 * c2, q1 = c1 * c1 + c3 * c3;
#pragma unroll
            for (int m = 4; m <= 16; m <<= 1) {
                s0 += __shfl_xor_sync(FULLM, s0, m);
                s1 += __shfl_xor_sync(FULLM, s1, m);
                q0 += __shfl_xor_sync(FULLM, q0, m);
                q1 += __shfl_xor_sync(FULLM, q1, m);
            }
            if (g == 0) {   // lanes 0-3: one contribution per column pair
                int col = nt * 8 + 2 * t;
                atomicAdd(&s_sum[col], s0);
                atomicAdd(&s_sum[col + 1], s1);
                atomicAdd(&s_sumsq[col], q0);
                atomicAdd(&s_sumsq[col + 1], q1);
            }

            float e0 = even ? c2 : c0;
            float e1 = even ? c3 : c1;
            float r0 = __shfl_xor_sync(FULLM, e0, 1);
            float r1 = __shfl_xor_sync(FULLM, e1, 1);
            float4 o;
            if (even) { o = make_float4(c0, c1, r0, r1); }
            else      { o = make_float4(r0, r1, c2, c3); }
            *(float4*)(outp + nt * 8) = o;
        }
    }

    // ---- flush block sums: 128 global atomics per block ----
    __syncthreads();
    if (tid < HH) {
        atomicAdd(&g_sum[tid], s_sum[tid]);
        atomicAdd(&g_sumsq[tid], s_sumsq[tid]);
    }
}

// ---------------- normalize (stats computed in-block): h = act(u*scale+shift) ----------------
// mode 1 block 0 additionally zeroes g_pooled for the upcoming atomic pooling.
__global__ void normalize_kernel(int mode, int n4,
                                 const float* __restrict__ gamma,
                                 const float* __restrict__ beta) {
    __shared__ float sc_s[HH], sh_s[HH];
    if (mode == 1 && blockIdx.x == 0) {
        for (int idx = threadIdx.x; idx < GG * HH; idx += blockDim.x)
            g_pooled[idx] = 0.f;
    }
    if (threadIdx.x < HH) {
        int c = threadIdx.x;
        float m = g_sum[c] * (1.f / NN);
        float v = g_sumsq[c] * (1.f / NN) - m * m;
        float rs = rsqrtf(v + BN_EPS);
        float sc = rs * gamma[c];
        sc_s[c] = sc;
        sh_s[c] = beta[c] - m * sc;
    }
    __syncthreads();

    int i = blockIdx.x * blockDim.x + threadIdx.x;
    if (i >= n4) return;
    int c0 = (i * 4) & 127;
    float4 sc = *(const float4*)(sc_s + c0);
    float4 sh = *(const float4*)(sh_s + c0);
    float4 v = ((const float4*)g_u)[i];
    v.x = fmaxf(v.x * sc.x + sh.x, 0.f);
    v.y = fmaxf(v.y * sc.y + sh.y, 0.f);
    v.z = fmaxf(v.z * sc.z + sh.z, 0.f);
    v.w = fmaxf(v.w * sc.w + sh.w, 0.f);
    if (mode == 1) {
        v.x = 1.f / (1.f + expf(-v.x));
        v.y = 1.f / (1.f + expf(-v.y));
        v.z = 1.f / (1.f + expf(-v.z));
        v.w = 1.f / (1.f + expf(-v.w));
    }
    ((float4*)g_h)[i] = v;
    if (mode == 0) ((float4*)g_y)[i] = v;   // layer2 accumulator init
}

// ---------------- per-graph mean pooling (4 chunks/graph, atomic partial sums) ----------------
__device__ __forceinline__ int lb_search(const void* bp, int target, bool i64) {
    int l = 0, r = NN;
    while (l < r) {
        int m = (l + r) >> 1;
        if (read_idx(bp, m, i64) < (long long)target) l = m + 1; else r = m;
    }
    return l;
}

__global__ void pool_kernel(const void* __restrict__ batchv) {
    const int g = blockIdx.x >> 2, chunk = blockIdx.x & 3;
    const int c = threadIdx.x;
    const bool i64 = (g_idx64 != 0);
    int lo = lb_search(batchv, g, i64);
    int hi = lb_search(batchv, g + 1, i64);
    int n = hi - lo;
    int c0 = lo + (int)(((long long)n * chunk) >> 2);
    int c1 = lo + (int)(((long long)n * (chunk + 1)) >> 2);

    float s0 = 0.f, s1 = 0.f, s2 = 0.f, s3 = 0.f;
    int i = c0;
    for (; i + 3 < c1; i += 4) {
        s0 += g_h[(size_t)i * HH + c];
        s1 += g_h[(size_t)(i + 1) * HH + c];
        s2 += g_h[(size_t)(i + 2) * HH + c];
        s3 += g_h[(size_t)(i + 3) * HH + c];
    }
    for (; i < c1; i++) s0 += g_h[(size_t)i * HH + c];
    float s = (s0 + s1) + (s2 + s3);
    if (c1 > c0) atomicAdd(&g_pooled[g * HH + c], s);
}

// ---------------- fused action MLP (divides pooled sums by counts) ----------------
__device__ __forceinline__ void mlp_layer(float* z, const float* p_s,
                                          const float* __restrict__ Wrow,
                                          float bias, float gamma, float beta) {
#pragma unroll
    for (int r = 0; r < GG; r++) z[r] = bias;
    for (int k = 0; k < HH; k += 4) {
        float4 w = *(const float4*)(Wrow + k);
#pragma unroll
        for (int r = 0; r < GG; r++) {
            float4 p = *(const float4*)(p_s + r * HH + k);
            z[r] += w.x * p.x + w.y * p.y + w.z * p.z + w.w * p.w;
        }
    }
    float m = 0.f, s2 = 0.f;
#pragma unroll
    for (int r = 0; r < GG; r++) { m += z[r]; s2 += z[r] * z[r]; }
    m *= (1.f / GG);
    float v = s2 * (1.f / GG) - m * m;
    float sc = rsqrtf(v + BN_EPS) * gamma;
    float sh = beta - m * sc;
#pragma unroll
    for (int r = 0; r < GG; r++) z[r] = fmaxf(z[r] * sc + sh, 0.f);
}

__global__ void __launch_bounds__(128) mlp_kernel(
    const void* __restrict__ batchv,
    const float* __restrict__ A1w, const float* __restrict__ A1b,
    const float* __restrict__ Ag1, const float* __restrict__ Ab1,
    const float* __restrict__ A2w, const float* __restrict__ A2b,
    const float* __restrict__ Ag2, const float* __restrict__ Ab2,
    const float* __restrict__ A3w, const float* __restrict__ A3b,
    float* __restrict__ out)
{
    __shared__ float p_s[GG * HH];
    __shared__ float inv_cnt[GG];
    const int c = threadIdx.x;
    const bool i64 = (g_idx64 != 0);
    if (c < GG) {
        int lo = lb_search(batchv, c, i64);
        int hi = lb_search(batchv, c + 1, i64);
        inv_cnt[c] = 1.f / fmaxf((float)(hi - lo), 1.f);
    }
    __syncthreads();
    for (int idx = c; idx < GG * HH; idx += 128)
        p_s[idx] = g_pooled[idx] * inv_cnt[idx >> 7];
    __syncthreads();

    float z[GG];
    mlp_layer(z, p_s, A1w + c * HH, A1b[c], Ag1[c], Ab1[c]);
    __syncthreads();
#pragma unroll
    for (int r = 0; r < GG; r++) p_s[r * HH + c] = z[r];
    __syncthreads();

    mlp_layer(z, p_s, A2w + c * HH, A2b[c], Ag2[c], Ab2[c]);
    __syncthreads();
#pragma unroll
    for (int r = 0; r < GG; r++) p_s[r * HH + c] = z[r];
    __syncthreads();

    for (int idx = c; idx < GG * AA; idx += 128) {
        int r = idx >> 4, a2 = idx & 15;
        float acc = A3b[a2];
        for (int k = 0; k < HH; k++) acc += p_s[r * HH + k] * A3w[a2 * HH + k];
        out[idx] = 1.f / (1.f + expf(-acc));
    }
}

// ---------------- host launch ----------------
extern "C" void kernel_launch(void* const* d_in, const int* in_sizes, int n_in,
                              void* d_out, int out_size) {
    int ix, iea, iei, ib;
    int iW1, ib1, iWe1, ibe1, ig1, ibt1, iW2, ib2, iWe2, ibe2, ig2, ibt2;
    int iA1w, iA1b, iAg1, iAb1, iA2w, iA2b, iAg2, iAb2, iA3w, iA3b;
    if (in_sizes[2] == 2 * EE || in_sizes[2] == 4 * EE) {
        ix = 0; iea = 1; iei = 2; ib = 3;
        iW1 = 4; ib1 = 5; iWe1 = 6; ibe1 = 7; ig1 = 8; ibt1 = 9;
        iW2 = 10; ib2 = 11; iWe2 = 12; ibe2 = 13; ig2 = 14; ibt2 = 15;
        iA1w = 16; iA1b = 17; iAg1 = 18; iAb1 = 19;
        iA2w = 20; iA2b = 21; iAg2 = 22; iAb2 = 23; iA3w = 24; iA3b = 25;
    } else {
        ix = 0; iea = 1;
        iW1 = 2; ib1 = 3; iWe1 = 4; ibe1 = 5; ig1 = 6; ibt1 = 7;
        iW2 = 8; ib2 = 9; iWe2 = 10; ibe2 = 11; ig2 = 12; ibt2 = 13;
        iA1w = 14; iA1b = 15; iAg1 = 16; iAb1 = 17;
        iA2w = 18; iA2b = 19; iAg2 = 20; iAb2 = 21; iA3w = 22; iA3b = 23;
        iei = 24; ib = 25;
    }

    const float* x   = (const float*)d_in[ix];
    const float* ea  = (const float*)d_in[iea];
    const void*  ei  = d_in[iei];
    const void*  bat = d_in[ib];
    float* out = (float*)d_out;

    const int n4 = NN * HH / 4;
    const int copy_blocks = (n4 + 255) / 256;
    const int edge_blocks = (NTILES + 63) / 64;      // 782
    const int gemm_blocks = (NN + 127) / 128;        // 391

    // launch indices: detect=0, copy=1, edge1=2, gemm1=3 (ncu-profiled slot)
    detect_kernel<<<1, 256>>>((const unsigned int*)ei);
    copy_init_kernel<<<copy_blocks, 256>>>((const float4*)x, n4);

    // ---- layer 1 ----
    edge_mma_kernel<<<edge_blocks, 256>>>(x, 0, ea, ei,
                                          (const float*)d_in[iWe1], (const float*)d_in[ibe1]);
    node_gemm_mma_kernel<<<gemm_blocks, 512>>>((const float*)d_in[iW1], (const float*)d_in[ib1]);
    normalize_kernel<<<copy_blocks, 256>>>(0, n4, (const float*)d_in[ig1], (const float*)d_in[ibt1]);

    // ---- layer 2 ----
    edge_mma_kernel<<<edge_blocks, 256>>>(x, 1, ea, ei,
                                          (const float*)d_in[iWe2], (const float*)d_in[ibe2]);
    node_gemm_mma_kernel<<<gemm_blocks, 512>>>((const float*)d_in[iW2], (const float*)d_in[ib2]);
    normalize_kernel<<<copy_blocks, 256>>>(1, n4, (const float*)d_in[ig2], (const float*)d_in[ibt2]);

    // ---- pool + MLP ----
    pool_kernel<<<GG * 4, 128>>>(bat);
    mlp_kernel<<<1, 128>>>(bat,
                           (const float*)d_in[iA1w], (const float*)d_in[iA1b],
                           (const float*)d_in[iAg1], (const float*)d_in[iAb1],
                           (const float*)d_in[iA2w], (const float*)d_in[iA2b],
                           (const float*)d_in[iAg2], (const float*)d_in[iAb2],
                           (const float*)d_in[iA3w], (const float*)d_in[iA3b], out);
}

// round 17
// speedup vs baseline: 1.0769x; 1.0061x over previous
#include <cuda_runtime.h>
#include <cuda_bf16.h>
#include <math.h>

#define NN 50000
#define EE 800000
#define HH 128
#define EDIM 32
#define GG 64
#define AA 16
#define BN_EPS 1e-5f
#define FULLM 0xffffffffu
#define TS 72   // smem tile row stride (floats): conflict-free STS.64/LDS.128

// ---------------- scratch (static device globals; no allocation) ----------------
__device__ float g_y[(size_t)NN * HH];
__device__ float g_u[(size_t)NN * HH];
__device__ float g_h[(size_t)NN * HH];
__device__ float g_sum[HH];
__device__ float g_sumsq[HH];
__device__ float g_pooled[GG * HH];
__device__ int   g_idx64;

// ---------------- int32/int64 index handling ----------------
__device__ __forceinline__ long long read_idx(const void* p, long long i, bool i64) {
    if (i64) return ((const long long*)p)[i];
    return (long long)((const int*)p)[i];
}

__global__ void detect_kernel(const unsigned int* __restrict__ w) {
    __shared__ int f;
    if (threadIdx.x == 0) f = 0;
    __syncthreads();
    int local = 0;
    for (int i = threadIdx.x * 2 + 1; i < 8192; i += 512)
        if (w[i]) local = 1;
    if (local) atomicOr(&f, 1);
    __syncthreads();
    if (threadIdx.x == 0) g_idx64 = f ? 0 : 1;
}

// ---------------- fast sigmoid: 1 MUFU instead of 2 (EX2+RCP) ----------------
__device__ __forceinline__ float fast_sigmoid(float x) {
    float t;
    asm("tanh.approx.f32 %0, %1;" : "=f"(t) : "f"(0.5f * x));
    return fmaf(0.5f, t, 0.5f);
}

// ---------------- bf16 2-split helpers ----------------
__device__ __forceinline__ unsigned pack2(float e0, float e1) {
    unsigned r;
    asm("cvt.rn.bf16x2.f32 %0, %1, %2;" : "=r"(r) : "f"(e1), "f"(e0));
    return r;
}
__device__ __forceinline__ void split2(float e0, float e1, unsigned& hi, unsigned& lo) {
    hi = pack2(e0, e1);
    float f0 = __uint_as_float(hi << 16);
    float f1 = __uint_as_float(hi & 0xffff0000u);
    lo = pack2(e0 - f0, e1 - f1);
}
__device__ __forceinline__ void mma_bf16(float& c0, float& c1, float& c2, float& c3,
                                         unsigned a0, unsigned a1, unsigned a2, unsigned a3,
                                         unsigned b0, unsigned b1) {
    asm volatile("mma.sync.aligned.m16n8k16.row.col.f32.bf16.bf16.f32 "
                 "{%0,%1,%2,%3}, {%4,%5,%6,%7}, {%8,%9}, {%0,%1,%2,%3};"
                 : "+f"(c0), "+f"(c1), "+f"(c2), "+f"(c3)
                 : "r"(a0), "r"(a1), "r"(a2), "r"(a3), "r"(b0), "r"(b1));
}

// Stage pre-split B fragments for one k32 block (1024 float4).
__device__ __forceinline__ void stage_bfrag(float4* bfrag, const float* __restrict__ Wmat,
                                            int ldw, int kbase, int tid, int nthreads) {
    for (int idx = tid; idx < 1024; idx += nthreads) {
        int nt = idx >> 6, kc = (idx >> 5) & 1, ln = idx & 31;
        int g2 = ln >> 2, t2 = ln & 3;
        int c = nt * 8 + g2;
        int k0 = kbase + 16 * kc + 2 * t2;
        float w00 = Wmat[c * ldw + k0];
        float w01 = Wmat[c * ldw + k0 + 1];
        float w10 = Wmat[c * ldw + k0 + 8];
        float w11 = Wmat[c * ldw + k0 + 9];
        unsigned bh0, bl0, bh1, bl1;
        split2(w00, w01, bh0, bl0);
        split2(w10, w11, bh1, bl1);
        bfrag[idx] = make_float4(__uint_as_float(bh0), __uint_as_float(bh1),
                                 __uint_as_float(bl0), __uint_as_float(bl1));
    }
}

// Load raw A data (2 rows x one k32 block) as 8 float2.
__device__ __forceinline__ void load_a_raw(const float* __restrict__ row0,
                                           const float* __restrict__ row1,
                                           int kbase, int t, float2 A[8]) {
#pragma unroll
    for (int kc = 0; kc < 2; kc++) {
        int k0 = kbase + 16 * kc + 2 * t;
        A[kc * 4 + 0] = *(const float2*)(row0 + k0);
        A[kc * 4 + 1] = *(const float2*)(row1 + k0);
        A[kc * 4 + 2] = *(const float2*)(row0 + k0 + 8);
        A[kc * 4 + 3] = *(const float2*)(row1 + k0 + 8);
    }
}
__device__ __forceinline__ void split_a(const float2 A[8],
                                        unsigned ahi[2][4], unsigned alo[2][4]) {
#pragma unroll
    for (int kc = 0; kc < 2; kc++) {
        split2(A[kc * 4 + 0].x, A[kc * 4 + 0].y, ahi[kc][0], alo[kc][0]);
        split2(A[kc * 4 + 1].x, A[kc * 4 + 1].y, ahi[kc][1], alo[kc][1]);
        split2(A[kc * 4 + 2].x, A[kc * 4 + 2].y, ahi[kc][2], alo[kc][2]);
        split2(A[kc * 4 + 3].x, A[kc * 4 + 3].y, ahi[kc][3], alo[kc][3]);
    }
}

// ---------------- y = src (copy) + zero BN stats ----------------
__global__ void copy_init_kernel(const float4* __restrict__ src, int n4) {
    if (blockIdx.x == 0 && threadIdx.x < HH) {
        g_sum[threadIdx.x] = 0.f;
        g_sumsq[threadIdx.x] = 0.f;
    }
    int i = blockIdx.x * blockDim.x + threadIdx.x;
    if (i < n4) ((float4*)g_y)[i] = src[i];
}

// ---------------- edge kernel: mma elin + smem-tiled coalesced epilogue ----------------
#define NTILES 50000         // EE/16
#define WTILES 8
__global__ void __launch_bounds__(256, 2) edge_mma_kernel(
    const float* __restrict__ xin_ext, int use_h,
    const float* __restrict__ ea,
    const void* __restrict__ eiv,
    const float* __restrict__ We,   // [128][32] row-major
    const float* __restrict__ be)
{
    __shared__ float4 bfrag[1024];        // 16KB
    __shared__ float be_s[HH];
    __shared__ float sbuf[8][16 * TS];    // per-warp [16 edges][64 cols padded]  36.9KB

    const int tid = threadIdx.x;
    // layer 2: re-zero BN stats for the upcoming gemm (edge2 strictly precedes gemm2,
    // and normalize1 — the last reader of the old stats — precedes edge2)
    if (use_h && blockIdx.x == 0 && tid < HH) {
        g_sum[tid] = 0.f;
        g_sumsq[tid] = 0.f;
    }
    stage_bfrag(bfrag, We, EDIM, 0, tid, 256);
    if (tid < HH) be_s[tid] = be[tid];
    __syncthreads();

    const float* __restrict__ xin = use_h ? g_h : xin_ext;
    const int lane = tid & 31, warp = tid >> 5;
    const int g = lane >> 2, t = lane & 3;
    const bool i64 = (g_idx64 != 0);
    const int half16 = lane >> 4;        // 0/1: which of 2 edges per epilogue iter
    const int li = lane & 15;            // column quad within edge half-row
    float* buf = sbuf[warp];
    const int base = (blockIdx.x * 8 + warp) * WTILES;

    int nt_here = NTILES - base;
    if (nt_here <= 0) return;
    if (nt_here > WTILES) nt_here = WTILES;

    for (int it = 0; it < nt_here; it++) {
        long long e0 = (long long)(base + it) * 16;
        int svC = 0, dvC = 0;
        if (lane < 16) {
            svC = (int)read_idx(eiv, e0 + lane, i64);
            dvC = (int)read_idx(eiv, (long long)EE + e0 + lane, i64);
        }
        float2 Ac[8];
        load_a_raw(ea + (size_t)(e0 + g) * EDIM, ea + (size_t)(e0 + g + 8) * EDIM, 0, t, Ac);

        unsigned ahi[2][4], alo[2][4];
        split_a(Ac, ahi, alo);

#pragma unroll
        for (int h = 0; h < 2; h++) {
            // ---- phase A: mma for cols [h*64, h*64+64), write to smem tile ----
#pragma unroll
            for (int ntl = 0; ntl < 8; ntl++) {
                int nt = h * 8 + ntl;
                float2 b2 = *(const float2*)(be_s + nt * 8 + 2 * t);
                float c0 = b2.x, c1 = b2.y, c2 = b2.x, c3 = b2.y;
#pragma unroll
                for (int kc = 0; kc < 2; kc++) {
                    float4 bf = bfrag[(nt * 2 + kc) * 32 + lane];
                    unsigned bh0 = __float_as_uint(bf.x), bh1 = __float_as_uint(bf.y);
                    unsigned bl0 = __float_as_uint(bf.z), bl1 = __float_as_uint(bf.w);
                    mma_bf16(c0, c1, c2, c3, ahi[kc][0], ahi[kc][1], ahi[kc][2], ahi[kc][3], bh0, bh1);
                    mma_bf16(c0, c1, c2, c3, alo[kc][0], alo[kc][1], alo[kc][2], alo[kc][3], bh0, bh1);
                    mma_bf16(c0, c1, c2, c3, ahi[kc][0], ahi[kc][1], ahi[kc][2], ahi[kc][3], bl0, bl1);
                }
                int cw = ntl * 8 + 2 * t;
                *(float2*)(buf + g * TS + cw)       = make_float2(c0, c1);
                *(float2*)(buf + (g + 8) * TS + cw) = make_float2(c2, c3);
            }
            __syncwarp();

            // ---- phase B: coalesced gather + relu + red, 2 edges x 64 cols per iter ----
#pragma unroll
            for (int g2 = 0; g2 < 4; g2++) {
                float4 m0, m1, xv0, xv1;
                int e0i = 4 * g2 + half16;       // edges e0i and e0i+2
                int e1i = e0i + 2;
                int s0 = __shfl_sync(FULLM, svC, e0i);
                int s1 = __shfl_sync(FULLM, svC, e1i);
                m0 = *(const float4*)(buf + e0i * TS + 4 * li);
                m1 = *(const float4*)(buf + e1i * TS + 4 * li);
                xv0 = *(const float4*)(xin + (size_t)s0 * HH + h * 64 + 4 * li);
                xv1 = *(const float4*)(xin + (size_t)s1 * HH + h * 64 + 4 * li);
                int d0 = __shfl_sync(FULLM, dvC, e0i);
                int d1 = __shfl_sync(FULLM, dvC, e1i);
                {
                    float o0 = fmaxf(m0.x + xv0.x, 0.f);
                    float o1 = fmaxf(m0.y + xv0.y, 0.f);
                    float o2 = fmaxf(m0.z + xv0.z, 0.f);
                    float o3 = fmaxf(m0.w + xv0.w, 0.f);
                    asm volatile("red.global.add.v4.f32 [%0], {%1,%2,%3,%4};"
                                 :: "l"(g_y + (size_t)d0 * HH + h * 64 + 4 * li),
                                    "f"(o0), "f"(o1), "f"(o2), "f"(o3) : "memory");
                }
                {
                    float o0 = fmaxf(m1.x + xv1.x, 0.f);
                    float o1 = fmaxf(m1.y + xv1.y, 0.f);
                    float o2 = fmaxf(m1.z + xv1.z, 0.f);
                    float o3 = fmaxf(m1.w + xv1.w, 0.f);
                    asm volatile("red.global.add.v4.f32 [%0], {%1,%2,%3,%4};"
                                 :: "l"(g_y + (size_t)d1 * HH + h * 64 + 4 * li),
                                    "f"(o0), "f"(o1), "f"(o2), "f"(o3) : "memory");
                }
            }
            __syncwarp();
        }
    }
}

// ---------------- node GEMM + fused BN sums, double-buffered, 2 blocks/SM ----------------
// 512 threads, 16 warps. Warp: 16 rows x 64 cols. Block: 128 rows x 128 cols.
__global__ void __launch_bounds__(512, 2) node_gemm_mma_kernel(
    const float* __restrict__ W,
    const float* __restrict__ b)
{
    __shared__ float4 bfrag[2][1024];   // double-buffered, 32KB
    __shared__ float b_s[HH];
    __shared__ float s_sum[HH], s_sumsq[HH];

    const int tid = threadIdx.x;
    const int lane = tid & 31, warp = tid >> 5;
    const int g = lane >> 2, t = lane & 3;
    const int colhalf = warp >> 3;
    const int rw = warp & 7;
    const int nt0 = colhalf * 8;
    const int rowbase = blockIdx.x * 128 + rw * 16;
    const bool active = (rowbase < NN);      // NN % 16 == 0
    const bool even = ((t & 1) == 0);
    const int cboff = (t & 2) ? 4 : 0;

    if (tid < HH) {
        b_s[tid] = b[tid];
        s_sum[tid] = 0.f;
        s_sumsq[tid] = 0.f;
    }

    float C[8][4];
#pragma unroll
    for (int nt = 0; nt < 8; nt++)
#pragma unroll
        for (int q = 0; q < 4; q++) C[nt][q] = 0.f;

    const float* row0 = g_y + (size_t)(rowbase + g) * HH;
    const float* row1 = g_y + (size_t)(rowbase + g + 8) * HH;

    stage_bfrag(bfrag[0], W, HH, 0, tid, 512);
    __syncthreads();

#pragma unroll
    for (int kb = 0; kb < 4; kb++) {
        // stage next k-block into the other buffer (overlaps with mma below)
        if (kb + 1 < 4)
            stage_bfrag(bfrag[(kb + 1) & 1], W, HH, (kb + 1) * 32, tid, 512);

        if (active) {
            const float4* bcur = bfrag[kb & 1];
            float2 A[8];
            load_a_raw(row0, row1, kb * 32, t, A);
            unsigned ahi[2][4], alo[2][4];
            split_a(A, ahi, alo);

#pragma unroll
            for (int ntl = 0; ntl < 8; ntl++) {
                int nt = nt0 + ntl;
#pragma unroll
                for (int kc = 0; kc < 2; kc++) {
                    float4 bf = bcur[(nt * 2 + kc) * 32 + lane];
                    unsigned bh0 = __float_as_uint(bf.x), bh1 = __float_as_uint(bf.y);
                    unsigned bl0 = __float_as_uint(bf.z), bl1 = __float_as_uint(bf.w);
                    mma_bf16(C[ntl][0], C[ntl][1], C[ntl][2], C[ntl][3],
                             ahi[kc][0], ahi[kc][1], ahi[kc][2], ahi[kc][3], bh0, bh1);
                    mma_bf16(C[ntl][0], C[ntl][1], C[ntl][2], C[ntl][3],
                             alo[kc][0], alo[kc][1], alo[kc][2], alo[kc][3], bh0, bh1);
                    mma_bf16(C[ntl][0], C[ntl][1], C[ntl][2], C[ntl][3],
                             ahi[kc][0], ahi[kc][1], ahi[kc][2], ahi[kc][3], bl0, bl1);
                }
            }
        }
        __syncthreads();   // staging of kb+1 done; all reads of bfrag[kb&1] done
    }

    if (active) {
        const int orow = rowbase + (even ? g : g + 8);
        float* outp = g_u + (size_t)orow * HH + cboff;
#pragma unroll
        for (int ntl = 0; ntl < 8; ntl++) {
            int nt = nt0 + ntl;
            float c0 = C[ntl][0] + b_s[nt * 8 + 2 * t];
            float c1 = C[ntl][1] + b_s[nt * 8 + 2 * t + 1];
            float c2 = C[ntl][2] + b_s[nt * 8 + 2 * t];
            float c3 = C[ntl][3] + b_s[nt * 8 + 2 * t + 1];

            // ---- BN column sums over this warp's 16 rows -> smem staging ----
            float s0 = c0 + c2, s1 = c1 + c3;
            float q0 = c0 * c0 + c2 * c2, q1 = c1 * c1 + c3 * c3;
#pragma unroll
            for (int m = 4; m <= 16; m <<= 1) {
                s0 += __shfl_xor_sync(FULLM, s0, m);
                s1 += __shfl_xor_sync(FULLM, s1, m);
                q0 += __shfl_xor_sync(FULLM, q0, m);
                q1 += __shfl_xor_sync(FULLM, q1, m);
            }
            if (g == 0) {   // lanes 0-3: one contribution per column pair
                int col = nt * 8 + 2 * t;
                atomicAdd(&s_sum[col], s0);
                atomicAdd(&s_sum[col + 1], s1);
                atomicAdd(&s_sumsq[col], q0);
                atomicAdd(&s_sumsq[col + 1], q1);
            }

            float e0 = even ? c2 : c0;
            float e1 = even ? c3 : c1;
            float r0 = __shfl_xor_sync(FULLM, e0, 1);
            float r1 = __shfl_xor_sync(FULLM, e1, 1);
            float4 o;
            if (even) { o = make_float4(c0, c1, r0, r1); }
            else      { o = make_float4(r0, r1, c2, c3); }
            *(float4*)(outp + nt * 8) = o;
        }
    }

    // ---- flush block sums: 128 global atomics per block ----
    __syncthreads();
    if (tid < HH) {
        atomicAdd(&g_sum[tid], s_sum[tid]);
        atomicAdd(&g_sumsq[tid], s_sumsq[tid]);
    }
}

// ---------------- normalize (stats computed in-block): h = act(u*scale+shift) ----------------
// mode 1 block 0 additionally zeroes g_pooled for the upcoming atomic pooling.
__global__ void normalize_kernel(int mode, int n4,
                                 const float* __restrict__ gamma,
                                 const float* __restrict__ beta) {
    __shared__ float sc_s[HH], sh_s[HH];
    if (mode == 1 && blockIdx.x == 0) {
        for (int idx = threadIdx.x; idx < GG * HH; idx += blockDim.x)
            g_pooled[idx] = 0.f;
    }
    if (threadIdx.x < HH) {
        int c = threadIdx.x;
        float m = g_sum[c] * (1.f / NN);
        float v = g_sumsq[c] * (1.f / NN) - m * m;
        float rs = rsqrtf(v + BN_EPS);
        float sc = rs * gamma[c];
        sc_s[c] = sc;
        sh_s[c] = beta[c] - m * sc;
    }
    __syncthreads();

    int i = blockIdx.x * blockDim.x + threadIdx.x;
    if (i >= n4) return;
    int c0 = (i * 4) & 127;
    float4 sc = *(const float4*)(sc_s + c0);
    float4 sh = *(const float4*)(sh_s + c0);
    float4 v = ((const float4*)g_u)[i];
    v.x = fmaxf(v.x * sc.x + sh.x, 0.f);
    v.y = fmaxf(v.y * sc.y + sh.y, 0.f);
    v.z = fmaxf(v.z * sc.z + sh.z, 0.f);
    v.w = fmaxf(v.w * sc.w + sh.w, 0.f);
    if (mode == 1) {
        v.x = fast_sigmoid(v.x);
        v.y = fast_sigmoid(v.y);
        v.z = fast_sigmoid(v.z);
        v.w = fast_sigmoid(v.w);
    }
    ((float4*)g_h)[i] = v;
    if (mode == 0) ((float4*)g_y)[i] = v;   // layer2 accumulator init
}

// ---------------- per-graph mean pooling (4 chunks/graph, atomic partial sums) ----------------
__device__ __forceinline__ int lb_search(const void* bp, int target, bool i64) {
    int l = 0, r = NN;
    while (l < r) {
        int m = (l + r) >> 1;
        if (read_idx(bp, m, i64) < (long long)target) l = m + 1; else r = m;
    }
    return l;
}

__global__ void pool_kernel(const void* __restrict__ batchv) {
    const int g = blockIdx.x >> 2, chunk = blockIdx.x & 3;
    const int c = threadIdx.x;
    const bool i64 = (g_idx64 != 0);
    int lo = lb_search(batchv, g, i64);
    int hi = lb_search(batchv, g + 1, i64);
    int n = hi - lo;
    int c0 = lo + (int)(((long long)n * chunk) >> 2);
    int c1 = lo + (int)(((long long)n * (chunk + 1)) >> 2);

    float s0 = 0.f, s1 = 0.f, s2 = 0.f, s3 = 0.f;
    int i = c0;
    for (; i + 3 < c1; i += 4) {
        s0 += g_h[(size_t)i * HH + c];
        s1 += g_h[(size_t)(i + 1) * HH + c];
        s2 += g_h[(size_t)(i + 2) * HH + c];
        s3 += g_h[(size_t)(i + 3) * HH + c];
    }
    for (; i < c1; i++) s0 += g_h[(size_t)i * HH + c];
    float s = (s0 + s1) + (s2 + s3);
    if (c1 > c0) atomicAdd(&g_pooled[g * HH + c], s);
}

// ---------------- fused action MLP (divides pooled sums by counts) ----------------
__device__ __forceinline__ void mlp_layer(float* z, const float* p_s,
                                          const float* __restrict__ Wrow,
                                          float bias, float gamma, float beta) {
#pragma unroll
    for (int r = 0; r < GG; r++) z[r] = bias;
    for (int k = 0; k < HH; k += 4) {
        float4 w = *(const float4*)(Wrow + k);
#pragma unroll
        for (int r = 0; r < GG; r++) {
            float4 p = *(const float4*)(p_s + r * HH + k);
            z[r] += w.x * p.x + w.y * p.y + w.z * p.z + w.w * p.w;
        }
    }
    float m = 0.f, s2 = 0.f;
#pragma unroll
    for (int r = 0; r < GG; r++) { m += z[r]; s2 += z[r] * z[r]; }
    m *= (1.f / GG);
    float v = s2 * (1.f / GG) - m * m;
    float sc = rsqrtf(v + BN_EPS) * gamma;
    float sh = beta - m * sc;
#pragma unroll
    for (int r = 0; r < GG; r++) z[r] = fmaxf(z[r] * sc + sh, 0.f);
}

__global__ void __launch_bounds__(128) mlp_kernel(
    const void* __restrict__ batchv,
    const float* __restrict__ A1w, const float* __restrict__ A1b,
    const float* __restrict__ Ag1, const float* __restrict__ Ab1,
    const float* __restrict__ A2w, const float* __restrict__ A2b,
    const float* __restrict__ Ag2, const float* __restrict__ Ab2,
    const float* __restrict__ A3w, const float* __restrict__ A3b,
    float* __restrict__ out)
{
    __shared__ float p_s[GG * HH];
    __shared__ float inv_cnt[GG];
    const int c = threadIdx.x;
    const bool i64 = (g_idx64 != 0);
    if (c < GG) {
        int lo = lb_search(batchv, c, i64);
        int hi = lb_search(batchv, c + 1, i64);
        inv_cnt[c] = 1.f / fmaxf((float)(hi - lo), 1.f);
    }
    __syncthreads();
    for (int idx = c; idx < GG * HH; idx += 128)
        p_s[idx] = g_pooled[idx] * inv_cnt[idx >> 7];
    __syncthreads();

    float z[GG];
    mlp_layer(z, p_s, A1w + c * HH, A1b[c], Ag1[c], Ab1[c]);
    __syncthreads();
#pragma unroll
    for (int r = 0; r < GG; r++) p_s[r * HH + c] = z[r];
    __syncthreads();

    mlp_layer(z, p_s, A2w + c * HH, A2b[c], Ag2[c], Ab2[c]);
    __syncthreads();
#pragma unroll
    for (int r = 0; r < GG; r++) p_s[r * HH + c] = z[r];
    __syncthreads();

    for (int idx = c; idx < GG * AA; idx += 128) {
        int r = idx >> 4, a2 = idx & 15;
        float acc = A3b[a2];
        for (int k = 0; k < HH; k++) acc += p_s[r * HH + k] * A3w[a2 * HH + k];
        out[idx] = fast_sigmoid(acc);
    }
}

// ---------------- host launch ----------------
extern "C" void kernel_launch(void* const* d_in, const int* in_sizes, int n_in,
                              void* d_out, int out_size) {
    int ix, iea, iei, ib;
    int iW1, ib1, iWe1, ibe1, ig1, ibt1, iW2, ib2, iWe2, ibe2, ig2, ibt2;
    int iA1w, iA1b, iAg1, iAb1, iA2w, iA2b, iAg2, iAb2, iA3w, iA3b;
    if (in_sizes[2] == 2 * EE || in_sizes[2] == 4 * EE) {
        ix = 0; iea = 1; iei = 2; ib = 3;
        iW1 = 4; ib1 = 5; iWe1 = 6; ibe1 = 7; ig1 = 8; ibt1 = 9;
        iW2 = 10; ib2 = 11; iWe2 = 12; ibe2 = 13; ig2 = 14; ibt2 = 15;
        iA1w = 16; iA1b = 17; iAg1 = 18; iAb1 = 19;
        iA2w = 20; iA2b = 21; iAg2 = 22; iAb2 = 23; iA3w = 24; iA3b = 25;
    } else {
        ix = 0; iea = 1;
        iW1 = 2; ib1 = 3; iWe1 = 4; ibe1 = 5; ig1 = 6; ibt1 = 7;
        iW2 = 8; ib2 = 9; iWe2 = 10; ibe2 = 11; ig2 = 12; ibt2 = 13;
        iA1w = 14; iA1b = 15; iAg1 = 16; iAb1 = 17;
        iA2w = 18; iA2b = 19; iAg2 = 20; iAb2 = 21; iA3w = 22; iA3b = 23;
        iei = 24; ib = 25;
    }

    const float* x   = (const float*)d_in[ix];
    const float* ea  = (const float*)d_in[iea];
    const void*  ei  = d_in[iei];
    const void*  bat = d_in[ib];
    float* out = (float*)d_out;

    const int n4 = NN * HH / 4;
    const int copy_blocks = (n4 + 255) / 256;
    const int edge_blocks = (NTILES + 63) / 64;      // 782
    const int gemm_blocks = (NN + 127) / 128;        // 391

    // launch indices: detect=0, copy=1, edge1=2, gemm1=3 (ncu-profiled slot)
    detect_kernel<<<1, 256>>>((const unsigned int*)ei);
    copy_init_kernel<<<copy_blocks, 256>>>((const float4*)x, n4);

    // ---- layer 1 ----
    edge_mma_kernel<<<edge_blocks, 256>>>(x, 0, ea, ei,
                                          (const float*)d_in[iWe1], (const float*)d_in[ibe1]);
    node_gemm_mma_kernel<<<gemm_blocks, 512>>>((const float*)d_in[iW1], (const float*)d_in[ib1]);
    normalize_kernel<<<copy_blocks, 256>>>(0, n4, (const float*)d_in[ig1], (const float*)d_in[ibt1]);

    // ---- layer 2 ----
    edge_mma_kernel<<<edge_blocks, 256>>>(x, 1, ea, ei,
                                          (const float*)d_in[iWe2], (const float*)d_in[ibe2]);
    node_gemm_mma_kernel<<<gemm_blocks, 512>>>((const float*)d_in[iW2], (const float*)d_in[ib2]);
    normalize_kernel<<<copy_blocks, 256>>>(1, n4, (const float*)d_in[ig2], (const float*)d_in[ibt2]);

    // ---- pool + MLP ----
    pool_kernel<<<GG * 4, 128>>>(bat);
    mlp_kernel<<<1, 128>>>(bat,
                           (const float*)d_in[iA1w], (const float*)d_in[iA1b],
                           (const float*)d_in[iAg1], (const float*)d_in[iAb1],
                           (const float*)d_in[iA2w], (const float*)d_in[iA2b],
                           (const float*)d_in[iAg2], (const float*)d_in[iAb2],
                           (const float*)d_in[iA3w], (const float*)d_in[iA3b], out);
}